// round 3
// baseline (speedup 1.0000x reference)
#include <cuda_runtime.h>
#include <cstdint>
#include <cstddef>

// ---------------------------------------------------------------------------
// GraphSAGE 3-layer forward, fp32, GB300 (sm_103a).
//   * transform-then-aggregate (aggregation is linear)
//   * dual-output GEMM: BM=128 x BN=256 tile, 8x16 per-thread microtile,
//     fma.rn.f32x2 packed math, software-pipelined tile loads
//   * per-call CSR build, gather aggregation (no feature atomics)
// Launch order places gemm0 at position 6 so ncu (-s 5 -c 1) profiles it.
// ---------------------------------------------------------------------------

#define NMAX 100000
#define EMAX 1600000

__device__ float g_SA[(size_t)NMAX * 128];
__device__ float g_SB[(size_t)NMAX * 128];
__device__ float g_Yb[(size_t)NMAX * 128];
__device__ float g_inv[NMAX];
__device__ int   g_deg[NMAX];
__device__ int   g_off[NMAX];
__device__ int   g_cur[NMAX];
__device__ int   g_csr[EMAX];
__device__ int   g_bsum[1024];
__device__ float g_W0[128 * 256];
__device__ float g_W1[128 * 256];
__device__ float g_W2[128 * 128];
__device__ float g_b0p[128];
__device__ float g_b1p[128];
__device__ float g_b2p[64];

// ---------------------------------------------------------------------------
// f32x2 helpers
// ---------------------------------------------------------------------------
__device__ __forceinline__ unsigned long long pk2(float x) {
    unsigned long long r;
    asm("mov.b64 %0, {%1, %1};" : "=l"(r) : "f"(x));
    return r;
}
__device__ __forceinline__ void ffma2(unsigned long long& d,
                                      unsigned long long a,
                                      unsigned long long b) {
    asm("fma.rn.f32x2 %0, %1, %2, %0;" : "+l"(d) : "l"(a), "l"(b));
}
__device__ __forceinline__ float2 upk(unsigned long long p) {
    float2 r;
    asm("mov.b64 {%0, %1}, %2;" : "=f"(r.x), "=f"(r.y) : "l"(p));
    return r;
}

// ---------------------------------------------------------------------------
// graph-structure kernels
// ---------------------------------------------------------------------------
__global__ void deg_zero_kernel(int* __restrict__ deg, int n) {
    int i = blockIdx.x * blockDim.x + threadIdx.x;
    if (i < n) deg[i] = 0;
}
__global__ void deg_count_kernel(int* __restrict__ deg, const int* __restrict__ dst, int e) {
    int i = blockIdx.x * blockDim.x + threadIdx.x;
    if (i < e) atomicAdd(&deg[dst[i]], 1);
}

__global__ __launch_bounds__(1024) void scan1_kernel(
    const int* __restrict__ deg, int* __restrict__ off, int* __restrict__ bsum, int n)
{
    __shared__ int sh[1024];
    int t = threadIdx.x;
    int i = blockIdx.x * 1024 + t;
    int v = (i < n) ? deg[i] : 0;
    sh[t] = v;
    __syncthreads();
    #pragma unroll
    for (int s = 1; s < 1024; s <<= 1) {
        int x = (t >= s) ? sh[t - s] : 0;
        __syncthreads();
        sh[t] += x;
        __syncthreads();
    }
    if (i < n) off[i] = sh[t] - v;
    if (t == 1023) bsum[blockIdx.x] = sh[t];
}

__global__ __launch_bounds__(1024) void scan2_kernel(int* __restrict__ bsum, int nb) {
    __shared__ int sh[1024];
    int t = threadIdx.x;
    int v = (t < nb) ? bsum[t] : 0;
    sh[t] = v;
    __syncthreads();
    #pragma unroll
    for (int s = 1; s < 1024; s <<= 1) {
        int x = (t >= s) ? sh[t - s] : 0;
        __syncthreads();
        sh[t] += x;
        __syncthreads();
    }
    if (t < nb) bsum[t] = sh[t] - v;
}

// finalize offsets, copy to cur, compute inv-degree (fused)
__global__ void scan3_inv_kernel(int* __restrict__ off, int* __restrict__ cur,
                                 const int* __restrict__ bsum,
                                 const int* __restrict__ deg,
                                 float* __restrict__ inv, int n) {
    int i = blockIdx.x * blockDim.x + threadIdx.x;
    if (i < n) {
        int o = off[i] + bsum[i >> 10];
        off[i] = o;
        cur[i] = o;
        int d = deg[i];
        inv[i] = 1.0f / (float)(d > 1 ? d : 1);
    }
}

__global__ void csr_fill_kernel(const int* __restrict__ src, const int* __restrict__ dst,
                                int* __restrict__ cur, int* __restrict__ csr, int e) {
    int i = blockIdx.x * blockDim.x + threadIdx.x;
    if (i < e) {
        int d = dst[i];
        int p = atomicAdd(&cur[d], 1);
        csr[p] = src[i];
    }
}

// ---------------------------------------------------------------------------
// one-shot weight prepack for all three layers
// W0/W1: [128, 256] = [Ws | Wn]; W2: [128, 128] = [Ws pad48->64 | Wn pad]
// ---------------------------------------------------------------------------
__global__ void pack_all_kernel(
    const float* __restrict__ ws0, const float* __restrict__ wn0, const float* __restrict__ b0,
    const float* __restrict__ ws1, const float* __restrict__ wn1, const float* __restrict__ b1,
    const float* __restrict__ ws2, const float* __restrict__ wn2, const float* __restrict__ b2,
    float* __restrict__ W0, float* __restrict__ W1, float* __restrict__ W2,
    float* __restrict__ b0p, float* __restrict__ b1p, float* __restrict__ b2p)
{
    int idx = blockIdx.x * blockDim.x + threadIdx.x;
    if (idx < 32768) {
        int k = idx >> 8, j = idx & 255;
        W0[idx] = (j < 128) ? ws0[k * 128 + j] : wn0[k * 128 + (j - 128)];
    } else if (idx < 65536) {
        int t = idx - 32768;
        int k = t >> 8, j = t & 255;
        W1[t] = (j < 128) ? ws1[k * 128 + j] : wn1[k * 128 + (j - 128)];
    } else if (idx < 65536 + 16384) {
        int t = idx - 65536;
        int k = t >> 7, j = t & 127;
        float w = 0.0f;
        if (j < 64) { if (j < 47) w = ws2[k * 47 + j]; }
        else        { int jj = j - 64; if (jj < 47) w = wn2[k * 47 + jj]; }
        W2[t] = w;
    }
    if (idx < 128) { b0p[idx] = b0[idx]; b1p[idx] = b1[idx]; }
    if (idx < 64)  { b2p[idx] = (idx < 47) ? b2[idx] : 0.0f; }
}

// ---------------------------------------------------------------------------
// Dual-output GEMM, f32x2, BM=128 x BN=2*HPAD, BK=16, 256 threads.
// Per thread: 8 rows x CN cols (CN=BN/16). A tile stored duplicated as f32x2.
// Software-pipelined global loads (regs prefetch across __syncthreads).
//   S[m, j] = (relu?)A[m,:] @ Ws[:, j] + bias[j]   (j < RS, stride RS)
//   Y[m, j] = (relu?)A[m,:] @ Wn[:, j]             (j < RS, stride RS)
// ---------------------------------------------------------------------------
template<int HPAD, int RS, bool RELU>
__global__ __launch_bounds__(256, 1) void gemm3_kernel(
    const float* __restrict__ A, int n,
    const float* __restrict__ Bp, const float* __restrict__ bp,
    float* __restrict__ S, float* __restrict__ Y)
{
    constexpr int BM = 128;
    constexpr int BK = 16;
    constexpr int K  = 128;
    constexpr int BN = 2 * HPAD;          // 256 or 128
    constexpr int NG = BN / 64;           // col groups per thread: 4 or 2
    constexpr int NP = 2 * NG;            // f32x2 accum pairs per row
    constexpr int BLD = (BK * BN) / 1024; // B float4 loads per thread: 4 or 2

    __shared__ unsigned long long As2[BK * BM];   // duplicated f32x2
    __shared__ float Bs[BK * BN];

    const int tid  = threadIdx.x;
    const int m0   = blockIdx.x * BM;
    const int tcol = tid & 15;
    const int trow = tid >> 4;            // rows trow*8 .. trow*8+7

    // loader mapping: each thread loads 8 A floats (one row, 8 k) + BLD B float4
    const int lr = tid >> 1;              // 0..127
    const int lk = (tid & 1) * 8;         // 0 or 8
    const int gr_load = m0 + lr;
    const bool arow_ok = (gr_load < n);

    unsigned long long acc[8][NP];
    #pragma unroll
    for (int r = 0; r < 8; r++)
        #pragma unroll
        for (int c = 0; c < NP; c++)
            acc[r][c] = 0ULL;

    float4 av0, av1;
    float4 bv[BLD];

    // ---- tile load (gmem -> regs) ----
    auto load_tile = [&](int kt) {
        av0 = make_float4(0.f, 0.f, 0.f, 0.f);
        av1 = av0;
        if (arow_ok) {
            const float* ap = A + (size_t)gr_load * K + kt + lk;
            av0 = *reinterpret_cast<const float4*>(ap);
            av1 = *reinterpret_cast<const float4*>(ap + 4);
        }
        #pragma unroll
        for (int i = 0; i < BLD; i++) {
            int a4 = (tid + i * 256) * 4;
            int k  = a4 / BN;
            int j  = a4 - k * BN;
            bv[i] = *reinterpret_cast<const float4*>(&Bp[(size_t)(kt + k) * BN + j]);
        }
    };

    // ---- tile store (regs -> smem) ----
    auto store_tile = [&]() {
        float a8[8] = {av0.x, av0.y, av0.z, av0.w, av1.x, av1.y, av1.z, av1.w};
        #pragma unroll
        for (int j = 0; j < 8; j++) {
            float x = a8[j];
            if (RELU) x = fmaxf(x, 0.f);
            As2[(lk + j) * BM + lr] = pk2(x);
        }
        #pragma unroll
        for (int i = 0; i < BLD; i++)
            *reinterpret_cast<float4*>(&Bs[(tid + i * 256) * 4]) = bv[i];
    };

    load_tile(0);

    for (int kt = 0; kt < K; kt += BK) {
        store_tile();
        __syncthreads();
        if (kt + BK < K) load_tile(kt + BK);

        #pragma unroll
        for (int kk = 0; kk < BK; kk++) {
            const ulonglong2* ap =
                reinterpret_cast<const ulonglong2*>(&As2[kk * BM + trow * 8]);
            ulonglong2 a01 = ap[0];
            ulonglong2 a23 = ap[1];
            ulonglong2 a45 = ap[2];
            ulonglong2 a67 = ap[3];
            unsigned long long ar[8] = {a01.x, a01.y, a23.x, a23.y,
                                        a45.x, a45.y, a67.x, a67.y};
            #pragma unroll
            for (int g = 0; g < NG; g++) {
                ulonglong2 b2 = *reinterpret_cast<const ulonglong2*>(
                    &Bs[kk * BN + g * 64 + tcol * 4]);
                #pragma unroll
                for (int r = 0; r < 8; r++) {
                    ffma2(acc[r][g * 2 + 0], ar[r], b2.x);
                    ffma2(acc[r][g * 2 + 1], ar[r], b2.y);
                }
            }
        }
        __syncthreads();
    }

    // ---- epilogue ----
    #pragma unroll
    for (int r = 0; r < 8; r++) {
        int gr = m0 + trow * 8 + r;
        if (gr >= n) continue;
        #pragma unroll
        for (int g = 0; g < NG; g++) {
            int cb = g * 64 + tcol * 4;
            float2 lo = upk(acc[r][g * 2 + 0]);
            float2 hi = upk(acc[r][g * 2 + 1]);
            if (cb < HPAD) {
                if (cb < RS) {
                    float4 bb = *reinterpret_cast<const float4*>(&bp[cb]);
                    float4 o = make_float4(lo.x + bb.x, lo.y + bb.y,
                                           hi.x + bb.z, hi.y + bb.w);
                    *reinterpret_cast<float4*>(S + (size_t)gr * RS + cb) = o;
                }
            } else {
                int cb2 = cb - HPAD;
                if (cb2 < RS) {
                    *reinterpret_cast<float4*>(Y + (size_t)gr * RS + cb2) =
                        make_float4(lo.x, lo.y, hi.x, hi.y);
                }
            }
        }
    }
}

// ---------------------------------------------------------------------------
// Gather aggregation: one warp per node, 4-way edge unroll.
//   S[node] += inv[node] * sum_{in-edges} Y[src]
// ---------------------------------------------------------------------------
template<int NV4, int RS>
__global__ __launch_bounds__(256) void agg_kernel(
    const float* __restrict__ Y, float* __restrict__ S,
    const int* __restrict__ csr, const int* __restrict__ off,
    const int* __restrict__ deg, const float* __restrict__ inv, int n)
{
    int w    = (blockIdx.x * blockDim.x + threadIdx.x) >> 5;
    int lane = threadIdx.x & 31;
    if (w >= n) return;
    if (lane >= NV4) return;

    int base = off[w];
    int dg   = deg[w];
    if (dg == 0) return;

    float4 a0 = make_float4(0.f, 0.f, 0.f, 0.f);
    float4 a1 = a0, a2 = a0, a3 = a0;

    int i = 0;
    for (; i + 3 < dg; i += 4) {
        int s0 = __ldg(&csr[base + i + 0]);
        int s1 = __ldg(&csr[base + i + 1]);
        int s2 = __ldg(&csr[base + i + 2]);
        int s3 = __ldg(&csr[base + i + 3]);
        float4 v0 = __ldg(reinterpret_cast<const float4*>(Y + (size_t)s0 * RS) + lane);
        float4 v1 = __ldg(reinterpret_cast<const float4*>(Y + (size_t)s1 * RS) + lane);
        float4 v2 = __ldg(reinterpret_cast<const float4*>(Y + (size_t)s2 * RS) + lane);
        float4 v3 = __ldg(reinterpret_cast<const float4*>(Y + (size_t)s3 * RS) + lane);
        a0.x += v0.x; a0.y += v0.y; a0.z += v0.z; a0.w += v0.w;
        a1.x += v1.x; a1.y += v1.y; a1.z += v1.z; a1.w += v1.w;
        a2.x += v2.x; a2.y += v2.y; a2.z += v2.z; a2.w += v2.w;
        a3.x += v3.x; a3.y += v3.y; a3.z += v3.z; a3.w += v3.w;
    }
    for (; i < dg; i++) {
        int s0 = __ldg(&csr[base + i]);
        float4 v0 = __ldg(reinterpret_cast<const float4*>(Y + (size_t)s0 * RS) + lane);
        a0.x += v0.x; a0.y += v0.y; a0.z += v0.z; a0.w += v0.w;
    }

    float iv = __ldg(&inv[w]);
    float4* sp = reinterpret_cast<float4*>(S + (size_t)w * RS) + lane;
    float4 cur = *sp;
    cur.x += iv * (a0.x + a1.x + a2.x + a3.x);
    cur.y += iv * (a0.y + a1.y + a2.y + a3.y);
    cur.z += iv * (a0.z + a1.z + a2.z + a3.z);
    cur.w += iv * (a0.w + a1.w + a2.w + a3.w);
    *sp = cur;
}

// ---------------------------------------------------------------------------
__global__ void copy_out_kernel(const float* __restrict__ S, float* __restrict__ out, int n) {
    int idx = blockIdx.x * blockDim.x + threadIdx.x;
    int total = n * 47;
    if (idx < total) {
        int r = idx / 47;
        int c = idx - r * 47;
        out[idx] = S[(size_t)r * 48 + c];
    }
}

// ---------------------------------------------------------------------------
extern "C" void kernel_launch(void* const* d_in, const int* in_sizes, int n_in,
                              void* d_out, int out_size)
{
    const float* x   = (const float*)d_in[0];
    const int*   src = (const int*)d_in[1];
    const int*   dst = (const int*)d_in[2];
    const float* ws0 = (const float*)d_in[3];
    const float* wn0 = (const float*)d_in[4];
    const float* b0  = (const float*)d_in[5];
    const float* ws1 = (const float*)d_in[6];
    const float* wn1 = (const float*)d_in[7];
    const float* b1  = (const float*)d_in[8];
    const float* ws2 = (const float*)d_in[9];
    const float* wn2 = (const float*)d_in[10];
    const float* b2  = (const float*)d_in[11];
    float* out = (float*)d_out;

    const int n = in_sizes[0] / 128;   // 100000
    const int e = in_sizes[1];         // 1600000

    float *SA, *SB, *Yb, *inv, *W0, *W1, *W2, *b0p, *b1p, *b2p;
    int *deg, *off, *cur, *csr, *bsum;
    cudaGetSymbolAddress((void**)&SA,   g_SA);
    cudaGetSymbolAddress((void**)&SB,   g_SB);
    cudaGetSymbolAddress((void**)&Yb,   g_Yb);
    cudaGetSymbolAddress((void**)&inv,  g_inv);
    cudaGetSymbolAddress((void**)&deg,  g_deg);
    cudaGetSymbolAddress((void**)&off,  g_off);
    cudaGetSymbolAddress((void**)&cur,  g_cur);
    cudaGetSymbolAddress((void**)&csr,  g_csr);
    cudaGetSymbolAddress((void**)&bsum, g_bsum);
    cudaGetSymbolAddress((void**)&W0,   g_W0);
    cudaGetSymbolAddress((void**)&W1,   g_W1);
    cudaGetSymbolAddress((void**)&W2,   g_W2);
    cudaGetSymbolAddress((void**)&b0p,  g_b0p);
    cudaGetSymbolAddress((void**)&b1p,  g_b1p);
    cudaGetSymbolAddress((void**)&b2p,  g_b2p);

    const int gblocks = (n + 127) / 128;
    const int ablocks = (n * 32 + 255) / 256;
    const int nb = (n + 1023) / 1024;

    // Launch order chosen so gemm0 is the 6th launch (ncu -s 5 -c 1 window).
    pack_all_kernel<<<(81920 + 255) / 256, 256>>>(
        ws0, wn0, b0, ws1, wn1, b1, ws2, wn2, b2,
        W0, W1, W2, b0p, b1p, b2p);                                   // 1
    deg_zero_kernel<<<(n + 255) / 256, 256>>>(deg, n);                // 2
    deg_count_kernel<<<(e + 255) / 256, 256>>>(deg, dst, e);          // 3
    scan1_kernel<<<nb, 1024>>>(deg, off, bsum, n);                    // 4
    scan2_kernel<<<1, 1024>>>(bsum, nb);                              // 5

    gemm3_kernel<128, 128, false><<<gblocks, 256>>>(x, n, W0, b0p, SA, Yb);   // 6 <- profiled

    scan3_inv_kernel<<<(n + 255) / 256, 256>>>(off, cur, bsum, deg, inv, n);  // 7
    csr_fill_kernel<<<(e + 255) / 256, 256>>>(src, dst, cur, csr, e);         // 8

    agg_kernel<32, 128><<<ablocks, 256>>>(Yb, SA, csr, off, deg, inv, n);     // 9

    gemm3_kernel<128, 128, true><<<gblocks, 256>>>(SA, n, W1, b1p, SB, Yb);   // 10
    agg_kernel<32, 128><<<ablocks, 256>>>(Yb, SB, csr, off, deg, inv, n);     // 11

    gemm3_kernel<64, 48, true><<<gblocks, 256>>>(SB, n, W2, b2p, SA, Yb);     // 12
    agg_kernel<12, 48><<<ablocks, 256>>>(Yb, SA, csr, off, deg, inv, n);      // 13

    copy_out_kernel<<<(n * 47 + 255) / 256, 256>>>(SA, out, n);               // 14
}

// round 4
// speedup vs baseline: 1.0461x; 1.0461x over previous
#include <cuda_runtime.h>
#include <cstdint>
#include <cstddef>

// ---------------------------------------------------------------------------
// GraphSAGE 3-layer forward, fp32, GB300 (sm_103a).
//   * transform-then-aggregate (aggregation is linear)
//   * dual-output GEMM: BM=64 x BN=2*HPAD, 4x16 microtile, fma.rn.f32x2,
//     reg-level software pipelining, 2 CTAs/SM
//   * per-call CSR build, gather aggregation (no feature atomics)
// gemm0 placed at my launch #4: harness pre-issues 2 launches, so overall
// launch #6 (ncu -s 5 -c 1 window) == my #4.
// ---------------------------------------------------------------------------

#define NMAX 100000
#define EMAX 1600000

__device__ float g_SA[(size_t)NMAX * 128];
__device__ float g_SB[(size_t)NMAX * 128];
__device__ float g_Yb[(size_t)NMAX * 128];
__device__ float g_inv[NMAX];
__device__ int   g_deg[NMAX];
__device__ int   g_off[NMAX];
__device__ int   g_cur[NMAX];
__device__ int   g_csr[EMAX];
__device__ int   g_bsum[1024];
__device__ float g_W0[128 * 256];
__device__ float g_W1[128 * 256];
__device__ float g_W2[128 * 128];
__device__ float g_b0p[128];
__device__ float g_b1p[128];
__device__ float g_b2p[64];

// ---------------------------------------------------------------------------
// f32x2 helpers
// ---------------------------------------------------------------------------
__device__ __forceinline__ unsigned long long pk2(float x) {
    unsigned long long r;
    asm("mov.b64 %0, {%1, %1};" : "=l"(r) : "f"(x));
    return r;
}
__device__ __forceinline__ void ffma2(unsigned long long& d,
                                      unsigned long long a,
                                      unsigned long long b) {
    asm("fma.rn.f32x2 %0, %1, %2, %0;" : "+l"(d) : "l"(a), "l"(b));
}
__device__ __forceinline__ float2 upk(unsigned long long p) {
    float2 r;
    asm("mov.b64 {%0, %1}, %2;" : "=f"(r.x), "=f"(r.y) : "l"(p));
    return r;
}

// ---------------------------------------------------------------------------
// graph-structure kernels
// ---------------------------------------------------------------------------
__global__ void deg_zero_kernel(int* __restrict__ deg, int n) {
    int i = blockIdx.x * blockDim.x + threadIdx.x;
    if (i < n) deg[i] = 0;
}
__global__ void deg_count_kernel(int* __restrict__ deg, const int* __restrict__ dst, int e) {
    int i = blockIdx.x * blockDim.x + threadIdx.x;
    if (i < e) atomicAdd(&deg[dst[i]], 1);
}

__global__ __launch_bounds__(1024) void scan1_kernel(
    const int* __restrict__ deg, int* __restrict__ off, int* __restrict__ bsum, int n)
{
    __shared__ int sh[1024];
    int t = threadIdx.x;
    int i = blockIdx.x * 1024 + t;
    int v = (i < n) ? deg[i] : 0;
    sh[t] = v;
    __syncthreads();
    #pragma unroll
    for (int s = 1; s < 1024; s <<= 1) {
        int x = (t >= s) ? sh[t - s] : 0;
        __syncthreads();
        sh[t] += x;
        __syncthreads();
    }
    if (i < n) off[i] = sh[t] - v;
    if (t == 1023) bsum[blockIdx.x] = sh[t];
}

__global__ __launch_bounds__(1024) void scan2_kernel(int* __restrict__ bsum, int nb) {
    __shared__ int sh[1024];
    int t = threadIdx.x;
    int v = (t < nb) ? bsum[t] : 0;
    sh[t] = v;
    __syncthreads();
    #pragma unroll
    for (int s = 1; s < 1024; s <<= 1) {
        int x = (t >= s) ? sh[t - s] : 0;
        __syncthreads();
        sh[t] += x;
        __syncthreads();
    }
    if (t < nb) bsum[t] = sh[t] - v;
}

__global__ void scan3_inv_kernel(int* __restrict__ off, int* __restrict__ cur,
                                 const int* __restrict__ bsum,
                                 const int* __restrict__ deg,
                                 float* __restrict__ inv, int n) {
    int i = blockIdx.x * blockDim.x + threadIdx.x;
    if (i < n) {
        int o = off[i] + bsum[i >> 10];
        off[i] = o;
        cur[i] = o;
        int d = deg[i];
        inv[i] = 1.0f / (float)(d > 1 ? d : 1);
    }
}

__global__ void csr_fill_kernel(const int* __restrict__ src, const int* __restrict__ dst,
                                int* __restrict__ cur, int* __restrict__ csr, int e) {
    int i = blockIdx.x * blockDim.x + threadIdx.x;
    if (i < e) {
        int d = dst[i];
        int p = atomicAdd(&cur[d], 1);
        csr[p] = src[i];
    }
}

// ---------------------------------------------------------------------------
// one-shot weight prepack
// ---------------------------------------------------------------------------
__global__ void pack_all_kernel(
    const float* __restrict__ ws0, const float* __restrict__ wn0, const float* __restrict__ b0,
    const float* __restrict__ ws1, const float* __restrict__ wn1, const float* __restrict__ b1,
    const float* __restrict__ ws2, const float* __restrict__ wn2, const float* __restrict__ b2,
    float* __restrict__ W0, float* __restrict__ W1, float* __restrict__ W2,
    float* __restrict__ b0p, float* __restrict__ b1p, float* __restrict__ b2p)
{
    int idx = blockIdx.x * blockDim.x + threadIdx.x;
    if (idx < 32768) {
        int k = idx >> 8, j = idx & 255;
        W0[idx] = (j < 128) ? ws0[k * 128 + j] : wn0[k * 128 + (j - 128)];
    } else if (idx < 65536) {
        int t = idx - 32768;
        int k = t >> 8, j = t & 255;
        W1[t] = (j < 128) ? ws1[k * 128 + j] : wn1[k * 128 + (j - 128)];
    } else if (idx < 65536 + 16384) {
        int t = idx - 65536;
        int k = t >> 7, j = t & 127;
        float w = 0.0f;
        if (j < 64) { if (j < 47) w = ws2[k * 47 + j]; }
        else        { int jj = j - 64; if (jj < 47) w = wn2[k * 47 + jj]; }
        W2[t] = w;
    }
    if (idx < 128) { b0p[idx] = b0[idx]; b1p[idx] = b1[idx]; }
    if (idx < 64)  { b2p[idx] = (idx < 47) ? b2[idx] : 0.0f; }
}

// ---------------------------------------------------------------------------
// Dual-output GEMM, f32x2, BM=64 x BN=2*HPAD, BK=16, 256 threads.
// 4 rows x 16 cols per thread (acc = 32 u64). Reg-level pipeline on tile loads.
//   S[m, j] = (relu?)A[m,:] @ Ws[:, j] + bias[j]   (j < RS, stride RS)
//   Y[m, j] = (relu?)A[m,:] @ Wn[:, j]             (j < RS, stride RS)
// ---------------------------------------------------------------------------
template<int HPAD, int RS, bool RELU>
__global__ __launch_bounds__(256, 2) void gemm3_kernel(
    const float* __restrict__ A, int n,
    const float* __restrict__ Bp, const float* __restrict__ bp,
    float* __restrict__ S, float* __restrict__ Y)
{
    constexpr int BM = 64;
    constexpr int BK = 16;
    constexpr int K  = 128;
    constexpr int BN = 2 * HPAD;          // 256 or 128
    constexpr int NG = BN / 64;           // 4 or 2
    constexpr int NP = 2 * NG;            // f32x2 pairs per row
    constexpr int BLD = (BK * BN) / 1024; // B float4 per thread: 4 or 2

    __shared__ unsigned long long As2[BK * BM];   // duplicated f32x2
    __shared__ float Bs[BK * BN];

    const int tid  = threadIdx.x;
    const int m0   = blockIdx.x * BM;
    const int tcol = tid & 15;
    const int trow = tid >> 4;            // rows trow*4 .. trow*4+3

    const int lr = tid >> 2;              // 0..63
    const int lk = (tid & 3) * 4;         // 0,4,8,12
    const int gr_load = m0 + lr;
    const bool arow_ok = (gr_load < n);

    unsigned long long acc[4][NP];
    #pragma unroll
    for (int r = 0; r < 4; r++)
        #pragma unroll
        for (int c = 0; c < NP; c++)
            acc[r][c] = 0ULL;

    float4 av;
    float4 bv[BLD];

    auto load_tile = [&](int kt) {
        av = make_float4(0.f, 0.f, 0.f, 0.f);
        if (arow_ok)
            av = *reinterpret_cast<const float4*>(A + (size_t)gr_load * K + kt + lk);
        #pragma unroll
        for (int i = 0; i < BLD; i++) {
            int a4 = (tid + i * 256) * 4;
            int k  = a4 / BN;
            int j  = a4 - k * BN;
            bv[i] = *reinterpret_cast<const float4*>(&Bp[(size_t)(kt + k) * BN + j]);
        }
    };

    auto store_tile = [&]() {
        float a4[4] = {av.x, av.y, av.z, av.w};
        #pragma unroll
        for (int j = 0; j < 4; j++) {
            float x = a4[j];
            if (RELU) x = fmaxf(x, 0.f);
            As2[(lk + j) * BM + lr] = pk2(x);
        }
        #pragma unroll
        for (int i = 0; i < BLD; i++)
            *reinterpret_cast<float4*>(&Bs[(tid + i * 256) * 4]) = bv[i];
    };

    load_tile(0);

    for (int kt = 0; kt < K; kt += BK) {
        store_tile();
        __syncthreads();
        if (kt + BK < K) load_tile(kt + BK);

        #pragma unroll
        for (int kk = 0; kk < BK; kk++) {
            const ulonglong2* ap =
                reinterpret_cast<const ulonglong2*>(&As2[kk * BM + trow * 4]);
            ulonglong2 aA = ap[0];
            ulonglong2 aB = ap[1];
            unsigned long long ar[4] = {aA.x, aA.y, aB.x, aB.y};
            #pragma unroll
            for (int g = 0; g < NG; g++) {
                ulonglong2 b2 = *reinterpret_cast<const ulonglong2*>(
                    &Bs[kk * BN + g * 64 + tcol * 4]);
                #pragma unroll
                for (int r = 0; r < 4; r++) {
                    ffma2(acc[r][g * 2 + 0], ar[r], b2.x);
                    ffma2(acc[r][g * 2 + 1], ar[r], b2.y);
                }
            }
        }
        __syncthreads();
    }

    // epilogue
    #pragma unroll
    for (int r = 0; r < 4; r++) {
        int gr = m0 + trow * 4 + r;
        if (gr >= n) continue;
        #pragma unroll
        for (int g = 0; g < NG; g++) {
            int cb = g * 64 + tcol * 4;
            float2 lo = upk(acc[r][g * 2 + 0]);
            float2 hi = upk(acc[r][g * 2 + 1]);
            if (cb < HPAD) {
                if (cb < RS) {
                    float4 bb = *reinterpret_cast<const float4*>(&bp[cb]);
                    float4 o = make_float4(lo.x + bb.x, lo.y + bb.y,
                                           hi.x + bb.z, hi.y + bb.w);
                    *reinterpret_cast<float4*>(S + (size_t)gr * RS + cb) = o;
                }
            } else {
                int cb2 = cb - HPAD;
                if (cb2 < RS) {
                    *reinterpret_cast<float4*>(Y + (size_t)gr * RS + cb2) =
                        make_float4(lo.x, lo.y, hi.x, hi.y);
                }
            }
        }
    }
}

// ---------------------------------------------------------------------------
// Gather aggregation: one warp per node, 4-way edge unroll.
// ---------------------------------------------------------------------------
template<int NV4, int RS>
__global__ __launch_bounds__(256) void agg_kernel(
    const float* __restrict__ Y, float* __restrict__ S,
    const int* __restrict__ csr, const int* __restrict__ off,
    const int* __restrict__ deg, const float* __restrict__ inv, int n)
{
    int w    = (blockIdx.x * blockDim.x + threadIdx.x) >> 5;
    int lane = threadIdx.x & 31;
    if (w >= n) return;
    if (lane >= NV4) return;

    int base = off[w];
    int dg   = deg[w];
    if (dg == 0) return;

    float4 a0 = make_float4(0.f, 0.f, 0.f, 0.f);
    float4 a1 = a0, a2 = a0, a3 = a0;

    int i = 0;
    for (; i + 3 < dg; i += 4) {
        int s0 = __ldg(&csr[base + i + 0]);
        int s1 = __ldg(&csr[base + i + 1]);
        int s2 = __ldg(&csr[base + i + 2]);
        int s3 = __ldg(&csr[base + i + 3]);
        float4 v0 = __ldg(reinterpret_cast<const float4*>(Y + (size_t)s0 * RS) + lane);
        float4 v1 = __ldg(reinterpret_cast<const float4*>(Y + (size_t)s1 * RS) + lane);
        float4 v2 = __ldg(reinterpret_cast<const float4*>(Y + (size_t)s2 * RS) + lane);
        float4 v3 = __ldg(reinterpret_cast<const float4*>(Y + (size_t)s3 * RS) + lane);
        a0.x += v0.x; a0.y += v0.y; a0.z += v0.z; a0.w += v0.w;
        a1.x += v1.x; a1.y += v1.y; a1.z += v1.z; a1.w += v1.w;
        a2.x += v2.x; a2.y += v2.y; a2.z += v2.z; a2.w += v2.w;
        a3.x += v3.x; a3.y += v3.y; a3.z += v3.z; a3.w += v3.w;
    }
    for (; i < dg; i++) {
        int s0 = __ldg(&csr[base + i]);
        float4 v0 = __ldg(reinterpret_cast<const float4*>(Y + (size_t)s0 * RS) + lane);
        a0.x += v0.x; a0.y += v0.y; a0.z += v0.z; a0.w += v0.w;
    }

    float iv = __ldg(&inv[w]);
    float4* sp = reinterpret_cast<float4*>(S + (size_t)w * RS) + lane;
    float4 cur = *sp;
    cur.x += iv * (a0.x + a1.x + a2.x + a3.x);
    cur.y += iv * (a0.y + a1.y + a2.y + a3.y);
    cur.z += iv * (a0.z + a1.z + a2.z + a3.z);
    cur.w += iv * (a0.w + a1.w + a2.w + a3.w);
    *sp = cur;
}

// ---------------------------------------------------------------------------
__global__ void copy_out_kernel(const float* __restrict__ S, float* __restrict__ out, int n) {
    int idx = blockIdx.x * blockDim.x + threadIdx.x;
    int total = n * 47;
    if (idx < total) {
        int r = idx / 47;
        int c = idx - r * 47;
        out[idx] = S[(size_t)r * 48 + c];
    }
}

// ---------------------------------------------------------------------------
extern "C" void kernel_launch(void* const* d_in, const int* in_sizes, int n_in,
                              void* d_out, int out_size)
{
    const float* x   = (const float*)d_in[0];
    const int*   src = (const int*)d_in[1];
    const int*   dst = (const int*)d_in[2];
    const float* ws0 = (const float*)d_in[3];
    const float* wn0 = (const float*)d_in[4];
    const float* b0  = (const float*)d_in[5];
    const float* ws1 = (const float*)d_in[6];
    const float* wn1 = (const float*)d_in[7];
    const float* b1  = (const float*)d_in[8];
    const float* ws2 = (const float*)d_in[9];
    const float* wn2 = (const float*)d_in[10];
    const float* b2  = (const float*)d_in[11];
    float* out = (float*)d_out;

    const int n = in_sizes[0] / 128;   // 100000
    const int e = in_sizes[1];         // 1600000

    float *SA, *SB, *Yb, *inv, *W0, *W1, *W2, *b0p, *b1p, *b2p;
    int *deg, *off, *cur, *csr, *bsum;
    cudaGetSymbolAddress((void**)&SA,   g_SA);
    cudaGetSymbolAddress((void**)&SB,   g_SB);
    cudaGetSymbolAddress((void**)&Yb,   g_Yb);
    cudaGetSymbolAddress((void**)&inv,  g_inv);
    cudaGetSymbolAddress((void**)&deg,  g_deg);
    cudaGetSymbolAddress((void**)&off,  g_off);
    cudaGetSymbolAddress((void**)&cur,  g_cur);
    cudaGetSymbolAddress((void**)&csr,  g_csr);
    cudaGetSymbolAddress((void**)&bsum, g_bsum);
    cudaGetSymbolAddress((void**)&W0,   g_W0);
    cudaGetSymbolAddress((void**)&W1,   g_W1);
    cudaGetSymbolAddress((void**)&W2,   g_W2);
    cudaGetSymbolAddress((void**)&b0p,  g_b0p);
    cudaGetSymbolAddress((void**)&b1p,  g_b1p);
    cudaGetSymbolAddress((void**)&b2p,  g_b2p);

    const int gblocks = (n + 63) / 64;
    const int ablocks = (n * 32 + 255) / 256;
    const int nb = (n + 1023) / 1024;

    // Harness pre-issues 2 launches; ncu -s 5 -c 1 profiles overall #6 = my #4.
    pack_all_kernel<<<(81920 + 255) / 256, 256>>>(
        ws0, wn0, b0, ws1, wn1, b1, ws2, wn2, b2,
        W0, W1, W2, b0p, b1p, b2p);                                   // my 1
    deg_zero_kernel<<<(n + 255) / 256, 256>>>(deg, n);                // my 2
    deg_count_kernel<<<(e + 255) / 256, 256>>>(deg, dst, e);          // my 3

    gemm3_kernel<128, 128, false><<<gblocks, 256>>>(x, n, W0, b0p, SA, Yb);   // my 4 <- profiled

    scan1_kernel<<<nb, 1024>>>(deg, off, bsum, n);                    // my 5
    scan2_kernel<<<1, 1024>>>(bsum, nb);                              // my 6
    scan3_inv_kernel<<<(n + 255) / 256, 256>>>(off, cur, bsum, deg, inv, n);  // my 7
    csr_fill_kernel<<<(e + 255) / 256, 256>>>(src, dst, cur, csr, e);         // my 8

    agg_kernel<32, 128><<<ablocks, 256>>>(Yb, SA, csr, off, deg, inv, n);     // my 9

    gemm3_kernel<128, 128, true><<<gblocks, 256>>>(SA, n, W1, b1p, SB, Yb);   // my 10
    agg_kernel<32, 128><<<ablocks, 256>>>(Yb, SB, csr, off, deg, inv, n);     // my 11

    gemm3_kernel<64, 48, true><<<gblocks, 256>>>(SB, n, W2, b2p, SA, Yb);     // my 12
    agg_kernel<12, 48><<<ablocks, 256>>>(Yb, SA, csr, off, deg, inv, n);      // my 13

    copy_out_kernel<<<(n * 47 + 255) / 256, 256>>>(SA, out, n);               // my 14
}

// round 6
// speedup vs baseline: 1.1786x; 1.1267x over previous
#include <cuda_runtime.h>
#include <cuda_bf16.h>
#include <cstdint>
#include <cstddef>

// ---------------------------------------------------------------------------
// GraphSAGE 3-layer forward, fp32 I/O, GB300 (sm_103a host, compute_103 PTX).
//   * transform-then-aggregate (aggregation is linear)
//   * GEMM on tensor cores via warp-level mma.sync bf16 (HMMA), hi/lo split:
//       A*B ~= Ah*Bh + Al*Bh + Ah*Bl   (fp32 accumulate, rel err ~1e-5)
//     (tcgen05 unavailable: harness PTX target is compute_103 without 'a')
//   * per-call CSR build, gather aggregation (no feature atomics)
// ---------------------------------------------------------------------------

#define NMAX 100000
#define EMAX 1600000

__device__ float g_SA[(size_t)NMAX * 128];
__device__ float g_SB[(size_t)NMAX * 128];
__device__ float g_Yb[(size_t)NMAX * 128];
__device__ float g_inv[NMAX];
__device__ int   g_deg[NMAX];
__device__ int   g_off[NMAX];
__device__ int   g_cur[NMAX];
__device__ int   g_csr[EMAX];
__device__ int   g_bsum[1024];
// prepacked bf16 weight images (hi image then lo image, swizzled smem layout)
__device__ __nv_bfloat16 g_B0[2 * 256 * 128];
__device__ __nv_bfloat16 g_B1[2 * 256 * 128];
__device__ __nv_bfloat16 g_B2[2 * 128 * 128];
__device__ float g_b0p[128];
__device__ float g_b1p[128];
__device__ float g_b2p[64];

// ---------------------------------------------------------------------------
// PTX helpers (warp mma / ldmatrix)
// ---------------------------------------------------------------------------
__device__ __forceinline__ uint32_t smem_u32(const void* p) {
    uint32_t a;
    asm("{ .reg .u64 t; cvta.to.shared.u64 t, %1; cvt.u32.u64 %0, t; }"
        : "=r"(a) : "l"(p));
    return a;
}

__device__ __forceinline__ void ldsm4(uint32_t* r, uint32_t addr) {
    asm volatile("ldmatrix.sync.aligned.m8n8.x4.shared.b16 {%0,%1,%2,%3}, [%4];"
        : "=r"(r[0]), "=r"(r[1]), "=r"(r[2]), "=r"(r[3]) : "r"(addr));
}

__device__ __forceinline__ void mma16816(float* c, const uint32_t* a, const uint32_t* b) {
    asm volatile(
        "mma.sync.aligned.m16n8k16.row.col.f32.bf16.bf16.f32 "
        "{%0,%1,%2,%3}, {%4,%5,%6,%7}, {%8,%9}, {%0,%1,%2,%3};"
        : "+f"(c[0]), "+f"(c[1]), "+f"(c[2]), "+f"(c[3])
        : "r"(a[0]), "r"(a[1]), "r"(a[2]), "r"(a[3]), "r"(b[0]), "r"(b[1]));
}

// ---------------------------------------------------------------------------
// graph-structure kernels
// ---------------------------------------------------------------------------
__global__ void deg_zero_kernel(int* __restrict__ deg, int n) {
    int i = blockIdx.x * blockDim.x + threadIdx.x;
    if (i < n) deg[i] = 0;
}
__global__ void deg_count_kernel(int* __restrict__ deg, const int* __restrict__ dst, int e) {
    int i = blockIdx.x * blockDim.x + threadIdx.x;
    if (i < e) atomicAdd(&deg[dst[i]], 1);
}

__global__ __launch_bounds__(1024) void scan1_kernel(
    const int* __restrict__ deg, int* __restrict__ off, int* __restrict__ bsum, int n)
{
    __shared__ int sh[1024];
    int t = threadIdx.x;
    int i = blockIdx.x * 1024 + t;
    int v = (i < n) ? deg[i] : 0;
    sh[t] = v;
    __syncthreads();
    #pragma unroll
    for (int s = 1; s < 1024; s <<= 1) {
        int x = (t >= s) ? sh[t - s] : 0;
        __syncthreads();
        sh[t] += x;
        __syncthreads();
    }
    if (i < n) off[i] = sh[t] - v;
    if (t == 1023) bsum[blockIdx.x] = sh[t];
}

__global__ __launch_bounds__(1024) void scan2_kernel(int* __restrict__ bsum, int nb) {
    __shared__ int sh[1024];
    int t = threadIdx.x;
    int v = (t < nb) ? bsum[t] : 0;
    sh[t] = v;
    __syncthreads();
    #pragma unroll
    for (int s = 1; s < 1024; s <<= 1) {
        int x = (t >= s) ? sh[t - s] : 0;
        __syncthreads();
        sh[t] += x;
        __syncthreads();
    }
    if (t < nb) bsum[t] = sh[t] - v;
}

__global__ void scan3_inv_kernel(int* __restrict__ off, int* __restrict__ cur,
                                 const int* __restrict__ bsum,
                                 const int* __restrict__ deg,
                                 float* __restrict__ inv, int n) {
    int i = blockIdx.x * blockDim.x + threadIdx.x;
    if (i < n) {
        int o = off[i] + bsum[i >> 10];
        off[i] = o;
        cur[i] = o;
        int d = deg[i];
        inv[i] = 1.0f / (float)(d > 1 ? d : 1);
    }
}

__global__ void csr_fill_kernel(const int* __restrict__ src, const int* __restrict__ dst,
                                int* __restrict__ cur, int* __restrict__ csr, int e) {
    int i = blockIdx.x * blockDim.x + threadIdx.x;
    if (i < e) {
        int d = dst[i];
        int p = atomicAdd(&cur[d], 1);
        csr[p] = src[i];
    }
}

// ---------------------------------------------------------------------------
// weight prepack: bf16 hi/lo images in the smem ldmatrix layout.
// Image: NB rows(n) x 128 cols(k), row = 256B, 16B chunks XOR-swizzled:
//   byte = nrow*256 + (((k>>3) ^ (nrow&7)) << 4) + (k&7)*2
// hi image at [0, NB*128), lo at [NB*128, 2*NB*128) elements.
// ---------------------------------------------------------------------------
__device__ __forceinline__ void pack_one(__nv_bfloat16* img, int NB, int nrow, int k, float w) {
    __nv_bfloat16 h = __float2bfloat16(w);
    __nv_bfloat16 l = __float2bfloat16(w - __bfloat162float(h));
    uint32_t off = (uint32_t)nrow * 256u
                 + ((((uint32_t)k >> 3) ^ ((uint32_t)nrow & 7u)) << 4)
                 + ((uint32_t)k & 7u) * 2u;
    char* hi = reinterpret_cast<char*>(img);
    char* lo = reinterpret_cast<char*>(img + (size_t)NB * 128);
    *reinterpret_cast<__nv_bfloat16*>(hi + off) = h;
    *reinterpret_cast<__nv_bfloat16*>(lo + off) = l;
}

__global__ void pack_all_kernel(
    const float* __restrict__ ws0, const float* __restrict__ wn0, const float* __restrict__ b0,
    const float* __restrict__ ws1, const float* __restrict__ wn1, const float* __restrict__ b1,
    const float* __restrict__ ws2, const float* __restrict__ wn2, const float* __restrict__ b2,
    __nv_bfloat16* __restrict__ B0, __nv_bfloat16* __restrict__ B1, __nv_bfloat16* __restrict__ B2,
    float* __restrict__ b0p, float* __restrict__ b1p, float* __restrict__ b2p)
{
    int idx = blockIdx.x * blockDim.x + threadIdx.x;
    if (idx < 32768) {                       // layer 0: NB=256
        int nrow = idx >> 7, k = idx & 127;
        float w = (nrow < 128) ? ws0[k * 128 + nrow] : wn0[k * 128 + (nrow - 128)];
        pack_one(B0, 256, nrow, k, w);
    } else if (idx < 65536) {                // layer 1
        int t = idx - 32768;
        int nrow = t >> 7, k = t & 127;
        float w = (nrow < 128) ? ws1[k * 128 + nrow] : wn1[k * 128 + (nrow - 128)];
        pack_one(B1, 256, nrow, k, w);
    } else if (idx < 65536 + 16384) {        // layer 2: NB=128, WC=47 pad 64
        int t = idx - 65536;
        int nrow = t >> 7, k = t & 127;
        float w = 0.0f;
        if (nrow < 64) { if (nrow < 47) w = ws2[k * 47 + nrow]; }
        else           { int jj = nrow - 64; if (jj < 47) w = wn2[k * 47 + jj]; }
        pack_one(B2, 128, nrow, k, w);
    }
    if (idx < 128) { b0p[idx] = b0[idx]; b1p[idx] = b1[idx]; }
    if (idx < 64)  { b2p[idx] = (idx < 47) ? b2[idx] : 0.0f; }
}

// ---------------------------------------------------------------------------
// HMMA GEMM: one 512-thread CTA per 128-row M-tile, K=128 resident, N=NB dual.
//   D[128, NB] = relu?(A)[128,128] @ W^T ; cols [0,NB/2)->S(+bias), rest->Y.
// 3 passes (Ah*Bh, Al*Bh, Ah*Bl) of 8 k16 steps, mma.m16n8k16 bf16.
// Warps 4(m) x 4(n); warp tile m32 x (NB/4).
// ---------------------------------------------------------------------------
template<int NB, int RS, bool RELU>
__global__ void __launch_bounds__(512, 1) gemm_mma_kernel(
    const float* __restrict__ A, int n,
    const __nv_bfloat16* __restrict__ Bimg, const float* __restrict__ bias,
    float* __restrict__ S, float* __restrict__ Y)
{
    constexpr int K   = 128;
    constexpr int WN  = NB / 4;     // warp n-extent: 64 or 32
    constexpr int NBT = WN / 16;    // B ldmatrix.x4 tiles per warp: 4 or 2
    constexpr int NT  = WN / 8;     // n8 mma tiles per warp: 8 or 4

    extern __shared__ char smem[];
    char* sAh = smem;                       // 32768
    char* sAl = smem + 32768;               // 32768
    char* sBh = smem + 65536;               // NB*256
    // sBl = sBh + NB*256

    const int tid    = threadIdx.x;
    const int wid    = tid >> 5;
    const int lane   = tid & 31;
    const int m0     = blockIdx.x * 128;
    const int warp_m = wid & 3;
    const int warp_n = wid >> 2;

    // --- B copy (prepacked, already swizzled): linear uint4 ---
    {
        const uint4* src = reinterpret_cast<const uint4*>(Bimg);
        uint4* dst = reinterpret_cast<uint4*>(sBh);
        constexpr int CNT = NB * 32;        // 2*NB*256 / 16
        #pragma unroll
        for (int i = 0; i < CNT / 512; i++)
            dst[tid + i * 512] = src[tid + i * 512];
    }

    // --- A fill: fp32 load, (relu), bf16 hi/lo split, swizzled 16B chunks ---
    {
        #pragma unroll
        for (int i = 0; i < 4; i++) {
            int c   = tid + i * 512;        // 0..2047 chunks of 8 elems
            int row = c >> 4;
            int c16 = c & 15;
            int gr  = m0 + row;
            float v[8];
            if (gr < n) {
                float4 p0 = *reinterpret_cast<const float4*>(A + (size_t)gr * K + c16 * 8);
                float4 p1 = *reinterpret_cast<const float4*>(A + (size_t)gr * K + c16 * 8 + 4);
                v[0]=p0.x; v[1]=p0.y; v[2]=p0.z; v[3]=p0.w;
                v[4]=p1.x; v[5]=p1.y; v[6]=p1.z; v[7]=p1.w;
            } else {
                #pragma unroll
                for (int q = 0; q < 8; q++) v[q] = 0.0f;
            }
            struct alignas(16) BF8 { __nv_bfloat16 b[8]; } hh, ll;
            #pragma unroll
            for (int q = 0; q < 8; q++) {
                float x = v[q];
                if (RELU) x = fmaxf(x, 0.0f);
                __nv_bfloat16 h = __float2bfloat16(x);
                hh.b[q] = h;
                ll.b[q] = __float2bfloat16(x - __bfloat162float(h));
            }
            uint32_t off = (uint32_t)row * 256u + (((uint32_t)(c16 ^ (row & 7))) << 4);
            *reinterpret_cast<BF8*>(sAh + off) = hh;
            *reinterpret_cast<BF8*>(sAl + off) = ll;
        }
    }
    __syncthreads();

    const uint32_t aAh = smem_u32(smem);
    const uint32_t aAl = aAh + 32768;
    const uint32_t aBh = aAh + 65536;
    const uint32_t aBl = aBh + NB * 256;

    // --- precomputed ldmatrix addressing ---
    int rA[2], swA[2];
    #pragma unroll
    for (int mt = 0; mt < 2; mt++) {
        int row = warp_m * 32 + mt * 16 + (lane & 15);
        rA[mt]  = row * 256;
        swA[mt] = row & 7;
    }
    const int hiA = lane >> 4;              // 0/1: k-chunk select
    int rB[NBT], swB[NBT];
    #pragma unroll
    for (int bt = 0; bt < NBT; bt++) {
        int row = warp_n * WN + bt * 16 + ((lane >> 4) << 3) + (lane & 7);
        rB[bt]  = row * 256;
        swB[bt] = row & 7;
    }
    const int hB = (lane >> 3) & 1;

    float acc[2][NT][4];
    #pragma unroll
    for (int mt = 0; mt < 2; mt++)
        #pragma unroll
        for (int nt = 0; nt < NT; nt++)
            #pragma unroll
            for (int q = 0; q < 4; q++)
                acc[mt][nt][q] = 0.0f;

    // --- 3 passes x 8 k16 steps ---
    #pragma unroll
    for (int pass = 0; pass < 3; pass++) {
        const uint32_t Ab = (pass == 1) ? aAl : aAh;
        const uint32_t Bb = (pass == 2) ? aBl : aBh;
        #pragma unroll
        for (int s = 0; s < 8; s++) {
            uint32_t a[2][4];
            #pragma unroll
            for (int mt = 0; mt < 2; mt++)
                ldsm4(a[mt], Ab + rA[mt] + (uint32_t)(((2 * s + hiA) ^ swA[mt]) << 4));
            uint32_t b[NBT][4];
            #pragma unroll
            for (int bt = 0; bt < NBT; bt++)
                ldsm4(b[bt], Bb + rB[bt] + (uint32_t)(((2 * s + hB) ^ swB[bt]) << 4));
            #pragma unroll
            for (int mt = 0; mt < 2; mt++)
                #pragma unroll
                for (int nt = 0; nt < NT; nt++)
                    mma16816(acc[mt][nt], a[mt], &b[nt >> 1][(nt & 1) * 2]);
        }
    }

    // --- epilogue: c0,c1 -> row g; c2,c3 -> row g+8; cols (lane&3)*2,+1 ---
    #pragma unroll
    for (int mt = 0; mt < 2; mt++) {
        int gr0 = m0 + warp_m * 32 + mt * 16 + (lane >> 2);
        #pragma unroll
        for (int nt = 0; nt < NT; nt++) {
            int J = warp_n * WN + nt * 8 + (lane & 3) * 2;
            #pragma unroll
            for (int rr = 0; rr < 2; rr++) {
                int gr = gr0 + rr * 8;
                if (gr >= n) continue;
                float c0 = acc[mt][nt][rr * 2 + 0];
                float c1 = acc[mt][nt][rr * 2 + 1];
                if (J < NB / 2) {
                    if (J < RS) {
                        float2 o = make_float2(c0 + bias[J], c1 + bias[J + 1]);
                        *reinterpret_cast<float2*>(S + (size_t)gr * RS + J) = o;
                    }
                } else {
                    int j2 = J - NB / 2;
                    if (j2 < RS) {
                        *reinterpret_cast<float2*>(Y + (size_t)gr * RS + j2) =
                            make_float2(c0, c1);
                    }
                }
            }
        }
    }
}

// ---------------------------------------------------------------------------
// Gather aggregation: one warp per node, 4-way edge unroll.
// ---------------------------------------------------------------------------
template<int NV4, int RS>
__global__ __launch_bounds__(256) void agg_kernel(
    const float* __restrict__ Y, float* __restrict__ S,
    const int* __restrict__ csr, const int* __restrict__ off,
    const int* __restrict__ deg, const float* __restrict__ inv, int n)
{
    int w    = (blockIdx.x * blockDim.x + threadIdx.x) >> 5;
    int lane = threadIdx.x & 31;
    if (w >= n) return;
    if (lane >= NV4) return;

    int base = off[w];
    int dg   = deg[w];
    if (dg == 0) return;

    float4 a0 = make_float4(0.f, 0.f, 0.f, 0.f);
    float4 a1 = a0, a2 = a0, a3 = a0;

    int i = 0;
    for (; i + 3 < dg; i += 4) {
        int s0 = __ldg(&csr[base + i + 0]);
        int s1 = __ldg(&csr[base + i + 1]);
        int s2 = __ldg(&csr[base + i + 2]);
        int s3 = __ldg(&csr[base + i + 3]);
        float4 v0 = __ldg(reinterpret_cast<const float4*>(Y + (size_t)s0 * RS) + lane);
        float4 v1 = __ldg(reinterpret_cast<const float4*>(Y + (size_t)s1 * RS) + lane);
        float4 v2 = __ldg(reinterpret_cast<const float4*>(Y + (size_t)s2 * RS) + lane);
        float4 v3 = __ldg(reinterpret_cast<const float4*>(Y + (size_t)s3 * RS) + lane);
        a0.x += v0.x; a0.y += v0.y; a0.z += v0.z; a0.w += v0.w;
        a1.x += v1.x; a1.y += v1.y; a1.z += v1.z; a1.w += v1.w;
        a2.x += v2.x; a2.y += v2.y; a2.z += v2.z; a2.w += v2.w;
        a3.x += v3.x; a3.y += v3.y; a3.z += v3.z; a3.w += v3.w;
    }
    for (; i < dg; i++) {
        int s0 = __ldg(&csr[base + i]);
        float4 v0 = __ldg(reinterpret_cast<const float4*>(Y + (size_t)s0 * RS) + lane);
        a0.x += v0.x; a0.y += v0.y; a0.z += v0.z; a0.w += v0.w;
    }

    float iv = __ldg(&inv[w]);
    float4* sp = reinterpret_cast<float4*>(S + (size_t)w * RS) + lane;
    float4 cur = *sp;
    cur.x += iv * (a0.x + a1.x + a2.x + a3.x);
    cur.y += iv * (a0.y + a1.y + a2.y + a3.y);
    cur.z += iv * (a0.z + a1.z + a2.z + a3.z);
    cur.w += iv * (a0.w + a1.w + a2.w + a3.w);
    *sp = cur;
}

// ---------------------------------------------------------------------------
__global__ void copy_out_kernel(const float* __restrict__ S, float* __restrict__ out, int n) {
    int idx = blockIdx.x * blockDim.x + threadIdx.x;
    int total = n * 47;
    if (idx < total) {
        int r = idx / 47;
        int c = idx - r * 47;
        out[idx] = S[(size_t)r * 48 + c];
    }
}

// ---------------------------------------------------------------------------
extern "C" void kernel_launch(void* const* d_in, const int* in_sizes, int n_in,
                              void* d_out, int out_size)
{
    const float* x   = (const float*)d_in[0];
    const int*   src = (const int*)d_in[1];
    const int*   dst = (const int*)d_in[2];
    const float* ws0 = (const float*)d_in[3];
    const float* wn0 = (const float*)d_in[4];
    const float* b0  = (const float*)d_in[5];
    const float* ws1 = (const float*)d_in[6];
    const float* wn1 = (const float*)d_in[7];
    const float* b1  = (const float*)d_in[8];
    const float* ws2 = (const float*)d_in[9];
    const float* wn2 = (const float*)d_in[10];
    const float* b2  = (const float*)d_in[11];
    float* out = (float*)d_out;

    const int n = in_sizes[0] / 128;   // 100000
    const int e = in_sizes[1];         // 1600000

    float *SA, *SB, *Yb, *inv, *b0p, *b1p, *b2p;
    __nv_bfloat16 *B0, *B1, *B2;
    int *deg, *off, *cur, *csr, *bsum;
    cudaGetSymbolAddress((void**)&SA,   g_SA);
    cudaGetSymbolAddress((void**)&SB,   g_SB);
    cudaGetSymbolAddress((void**)&Yb,   g_Yb);
    cudaGetSymbolAddress((void**)&inv,  g_inv);
    cudaGetSymbolAddress((void**)&deg,  g_deg);
    cudaGetSymbolAddress((void**)&off,  g_off);
    cudaGetSymbolAddress((void**)&cur,  g_cur);
    cudaGetSymbolAddress((void**)&csr,  g_csr);
    cudaGetSymbolAddress((void**)&bsum, g_bsum);
    cudaGetSymbolAddress((void**)&B0,   g_B0);
    cudaGetSymbolAddress((void**)&B1,   g_B1);
    cudaGetSymbolAddress((void**)&B2,   g_B2);
    cudaGetSymbolAddress((void**)&b0p,  g_b0p);
    cudaGetSymbolAddress((void**)&b1p,  g_b1p);
    cudaGetSymbolAddress((void**)&b2p,  g_b2p);

    // dynamic smem: 64KB A + 2*NB*256 B
    const int SMEM_BIG   = 65536 + 2 * 256 * 256;   // 196608
    const int SMEM_SMALL = 65536 + 2 * 128 * 256;   // 131072
    cudaFuncSetAttribute(gemm_mma_kernel<256, 128, false>,
                         cudaFuncAttributeMaxDynamicSharedMemorySize, SMEM_BIG);
    cudaFuncSetAttribute(gemm_mma_kernel<256, 128, true>,
                         cudaFuncAttributeMaxDynamicSharedMemorySize, SMEM_BIG);
    cudaFuncSetAttribute(gemm_mma_kernel<128, 48, true>,
                         cudaFuncAttributeMaxDynamicSharedMemorySize, SMEM_SMALL);

    const int gblocks = (n + 127) / 128;   // 782
    const int ablocks = (n * 32 + 255) / 256;
    const int nb = (n + 1023) / 1024;

    // Harness pre-issues 2 launches; ncu -s 5 -c 1 profiles overall #6 = my #4.
    pack_all_kernel<<<(81920 + 255) / 256, 256>>>(
        ws0, wn0, b0, ws1, wn1, b1, ws2, wn2, b2,
        B0, B1, B2, b0p, b1p, b2p);                                   // my 1
    deg_zero_kernel<<<(n + 255) / 256, 256>>>(deg, n);                // my 2
    deg_count_kernel<<<(e + 255) / 256, 256>>>(deg, dst, e);          // my 3

    gemm_mma_kernel<256, 128, false><<<gblocks, 512, SMEM_BIG>>>(
        x, n, B0, b0p, SA, Yb);                                       // my 4 <- profiled

    scan1_kernel<<<nb, 1024>>>(deg, off, bsum, n);                    // my 5
    scan2_kernel<<<1, 1024>>>(bsum, nb);                              // my 6
    scan3_inv_kernel<<<(n + 255) / 256, 256>>>(off, cur, bsum, deg, inv, n);  // my 7
    csr_fill_kernel<<<(e + 255) / 256, 256>>>(src, dst, cur, csr, e);         // my 8

    agg_kernel<32, 128><<<ablocks, 256>>>(Yb, SA, csr, off, deg, inv, n);     // my 9

    gemm_mma_kernel<256, 128, true><<<gblocks, 512, SMEM_BIG>>>(
        SA, n, B1, b1p, SB, Yb);                                              // my 10
    agg_kernel<32, 128><<<ablocks, 256>>>(Yb, SB, csr, off, deg, inv, n);     // my 11

    gemm_mma_kernel<128, 48, true><<<gblocks, 512, SMEM_SMALL>>>(
        SB, n, B2, b2p, SA, Yb);                                              // my 12
    agg_kernel<12, 48><<<ablocks, 256>>>(Yb, SA, csr, off, deg, inv, n);      // my 13

    copy_out_kernel<<<(n * 47 + 255) / 256, 256>>>(SA, out, n);               // my 14
}

// round 7
// speedup vs baseline: 1.2156x; 1.0314x over previous
#include <cuda_runtime.h>
#include <cuda_bf16.h>
#include <cstdint>
#include <cstddef>

// ---------------------------------------------------------------------------
// GraphSAGE 3-layer forward, fp32 I/O, GB300 (sm_103a host, compute_103 PTX).
//   * transform-then-aggregate (aggregation is linear)
//   * GEMM: warp-level mma.sync bf16 (HMMA), hi/lo split (3 passes), now
//     PERSISTENT: B resident in smem, CTA loops M-tiles, next-tile A loads
//     overlapped with current-tile epilogue stores.
//   * per-call CSR build, gather aggregation (no feature atomics)
// ---------------------------------------------------------------------------

#define NMAX 100000
#define EMAX 1600000

__device__ float g_SA[(size_t)NMAX * 128];
__device__ float g_SB[(size_t)NMAX * 128];
__device__ float g_Yb[(size_t)NMAX * 128];
__device__ float g_inv[NMAX];
__device__ int   g_deg[NMAX];
__device__ int   g_off[NMAX];
__device__ int   g_cur[NMAX];
__device__ int   g_csr[EMAX];
__device__ int   g_bsum[1024];
// prepacked bf16 weight images (hi image then lo image, swizzled smem layout)
__device__ __nv_bfloat16 g_B0[2 * 256 * 128];
__device__ __nv_bfloat16 g_B1[2 * 256 * 128];
__device__ __nv_bfloat16 g_B2[2 * 128 * 128];
__device__ float g_b0p[128];
__device__ float g_b1p[128];
__device__ float g_b2p[64];

// ---------------------------------------------------------------------------
// PTX helpers (warp mma / ldmatrix)
// ---------------------------------------------------------------------------
__device__ __forceinline__ uint32_t smem_u32(const void* p) {
    uint32_t a;
    asm("{ .reg .u64 t; cvta.to.shared.u64 t, %1; cvt.u32.u64 %0, t; }"
        : "=r"(a) : "l"(p));
    return a;
}

__device__ __forceinline__ void ldsm4(uint32_t* r, uint32_t addr) {
    asm volatile("ldmatrix.sync.aligned.m8n8.x4.shared.b16 {%0,%1,%2,%3}, [%4];"
        : "=r"(r[0]), "=r"(r[1]), "=r"(r[2]), "=r"(r[3]) : "r"(addr));
}

__device__ __forceinline__ void mma16816(float* c, const uint32_t* a, const uint32_t* b) {
    asm volatile(
        "mma.sync.aligned.m16n8k16.row.col.f32.bf16.bf16.f32 "
        "{%0,%1,%2,%3}, {%4,%5,%6,%7}, {%8,%9}, {%0,%1,%2,%3};"
        : "+f"(c[0]), "+f"(c[1]), "+f"(c[2]), "+f"(c[3])
        : "r"(a[0]), "r"(a[1]), "r"(a[2]), "r"(a[3]), "r"(b[0]), "r"(b[1]));
}

// ---------------------------------------------------------------------------
// graph-structure kernels
// ---------------------------------------------------------------------------
__global__ void deg_zero_kernel(int* __restrict__ deg, int n) {
    int i = blockIdx.x * blockDim.x + threadIdx.x;
    if (i < n) deg[i] = 0;
}
__global__ void deg_count_kernel(int* __restrict__ deg, const int* __restrict__ dst, int e) {
    int i = blockIdx.x * blockDim.x + threadIdx.x;
    if (i < e) atomicAdd(&deg[dst[i]], 1);
}

__global__ __launch_bounds__(1024) void scan1_kernel(
    const int* __restrict__ deg, int* __restrict__ off, int* __restrict__ bsum, int n)
{
    __shared__ int sh[1024];
    int t = threadIdx.x;
    int i = blockIdx.x * 1024 + t;
    int v = (i < n) ? deg[i] : 0;
    sh[t] = v;
    __syncthreads();
    #pragma unroll
    for (int s = 1; s < 1024; s <<= 1) {
        int x = (t >= s) ? sh[t - s] : 0;
        __syncthreads();
        sh[t] += x;
        __syncthreads();
    }
    if (i < n) off[i] = sh[t] - v;
    if (t == 1023) bsum[blockIdx.x] = sh[t];
}

__global__ __launch_bounds__(1024) void scan2_kernel(int* __restrict__ bsum, int nb) {
    __shared__ int sh[1024];
    int t = threadIdx.x;
    int v = (t < nb) ? bsum[t] : 0;
    sh[t] = v;
    __syncthreads();
    #pragma unroll
    for (int s = 1; s < 1024; s <<= 1) {
        int x = (t >= s) ? sh[t - s] : 0;
        __syncthreads();
        sh[t] += x;
        __syncthreads();
    }
    if (t < nb) bsum[t] = sh[t] - v;
}

__global__ void scan3_inv_kernel(int* __restrict__ off, int* __restrict__ cur,
                                 const int* __restrict__ bsum,
                                 const int* __restrict__ deg,
                                 float* __restrict__ inv, int n) {
    int i = blockIdx.x * blockDim.x + threadIdx.x;
    if (i < n) {
        int o = off[i] + bsum[i >> 10];
        off[i] = o;
        cur[i] = o;
        int d = deg[i];
        inv[i] = 1.0f / (float)(d > 1 ? d : 1);
    }
}

__global__ void csr_fill_kernel(const int* __restrict__ src, const int* __restrict__ dst,
                                int* __restrict__ cur, int* __restrict__ csr, int e) {
    int i = blockIdx.x * blockDim.x + threadIdx.x;
    if (i < e) {
        int d = dst[i];
        int p = atomicAdd(&cur[d], 1);
        csr[p] = src[i];
    }
}

// ---------------------------------------------------------------------------
// weight prepack: bf16 hi/lo images in the smem ldmatrix layout.
//   byte = nrow*256 + (((k>>3) ^ (nrow&7)) << 4) + (k&7)*2
// hi image at [0, NB*128), lo at [NB*128, 2*NB*128) elements.
// ---------------------------------------------------------------------------
__device__ __forceinline__ void pack_one(__nv_bfloat16* img, int NB, int nrow, int k, float w) {
    __nv_bfloat16 h = __float2bfloat16(w);
    __nv_bfloat16 l = __float2bfloat16(w - __bfloat162float(h));
    uint32_t off = (uint32_t)nrow * 256u
                 + ((((uint32_t)k >> 3) ^ ((uint32_t)nrow & 7u)) << 4)
                 + ((uint32_t)k & 7u) * 2u;
    char* hi = reinterpret_cast<char*>(img);
    char* lo = reinterpret_cast<char*>(img + (size_t)NB * 128);
    *reinterpret_cast<__nv_bfloat16*>(hi + off) = h;
    *reinterpret_cast<__nv_bfloat16*>(lo + off) = l;
}

__global__ void pack_all_kernel(
    const float* __restrict__ ws0, const float* __restrict__ wn0, const float* __restrict__ b0,
    const float* __restrict__ ws1, const float* __restrict__ wn1, const float* __restrict__ b1,
    const float* __restrict__ ws2, const float* __restrict__ wn2, const float* __restrict__ b2,
    __nv_bfloat16* __restrict__ B0, __nv_bfloat16* __restrict__ B1, __nv_bfloat16* __restrict__ B2,
    float* __restrict__ b0p, float* __restrict__ b1p, float* __restrict__ b2p)
{
    int idx = blockIdx.x * blockDim.x + threadIdx.x;
    if (idx < 32768) {                       // layer 0: NB=256
        int nrow = idx >> 7, k = idx & 127;
        float w = (nrow < 128) ? ws0[k * 128 + nrow] : wn0[k * 128 + (nrow - 128)];
        pack_one(B0, 256, nrow, k, w);
    } else if (idx < 65536) {                // layer 1
        int t = idx - 32768;
        int nrow = t >> 7, k = t & 127;
        float w = (nrow < 128) ? ws1[k * 128 + nrow] : wn1[k * 128 + (nrow - 128)];
        pack_one(B1, 256, nrow, k, w);
    } else if (idx < 65536 + 16384) {        // layer 2: NB=128, WC=47 pad 64
        int t = idx - 65536;
        int nrow = t >> 7, k = t & 127;
        float w = 0.0f;
        if (nrow < 64) { if (nrow < 47) w = ws2[k * 47 + nrow]; }
        else           { int jj = nrow - 64; if (jj < 47) w = wn2[k * 47 + jj]; }
        pack_one(B2, 128, nrow, k, w);
    }
    if (idx < 128) { b0p[idx] = b0[idx]; b1p[idx] = b1[idx]; }
    if (idx < 64)  { b2p[idx] = (idx < 47) ? b2[idx] : 0.0f; }
}

// ---------------------------------------------------------------------------
// PERSISTENT HMMA GEMM: grid = #SMs; B + bias resident in smem; CTA loops
// over 128-row M-tiles. Next tile's A global loads overlap current epilogue.
//   D[128, NB] = relu?(A)[128,128] @ W^T ; cols [0,NB/2)->S(+bias), rest->Y.
// 3 passes (Ah*Bh, Al*Bh, Ah*Bl) of 8 k16 steps, mma.m16n8k16 bf16.
// Warps 4(m) x 4(n); warp tile m32 x (NB/4). 512 threads.
// ---------------------------------------------------------------------------
template<int NB, int RS, bool RELU>
__global__ void __launch_bounds__(512, 1) gemm_mma_kernel(
    const float* __restrict__ A, int n, int ntiles,
    const __nv_bfloat16* __restrict__ Bimg, const float* __restrict__ bias,
    float* __restrict__ S, float* __restrict__ Y)
{
    constexpr int K   = 128;
    constexpr int WN  = NB / 4;     // warp n-extent: 64 or 32
    constexpr int NBT = WN / 16;    // B ldmatrix.x4 tiles per warp
    constexpr int NT  = WN / 8;     // n8 mma tiles per warp
    constexpr int HC  = NB / 2;

    extern __shared__ char smem[];
    char*  sAh   = smem;                            // 32768
    char*  sAl   = smem + 32768;                    // 32768
    char*  sB    = smem + 65536;                    // 2*NB*256
    float* sBias = reinterpret_cast<float*>(smem + 65536 + 2 * NB * 256);

    const int tid    = threadIdx.x;
    const int wid    = tid >> 5;
    const int lane   = tid & 31;
    const int warp_m = wid & 3;
    const int warp_n = wid >> 2;

    // --- B + bias: resident copy, once ---
    {
        const uint4* src = reinterpret_cast<const uint4*>(Bimg);
        uint4* dst = reinterpret_cast<uint4*>(sB);
        constexpr int CNT = NB * 32;        // 2*NB*256 / 16
        #pragma unroll
        for (int i = 0; i < CNT / 512; i++)
            dst[tid + i * 512] = src[tid + i * 512];
        if (tid < HC) sBias[tid] = bias[tid];
    }

    const uint32_t aAh = smem_u32(smem);
    const uint32_t aAl = aAh + 32768;
    const uint32_t aBh = aAh + 65536;
    const uint32_t aBl = aBh + NB * 256;

    // --- ldmatrix addressing (fixed per thread) ---
    int rA[2], swA[2];
    #pragma unroll
    for (int mt = 0; mt < 2; mt++) {
        int row = warp_m * 32 + mt * 16 + (lane & 15);
        rA[mt]  = row * 256;
        swA[mt] = row & 7;
    }
    const int hiA = lane >> 4;
    int rB[NBT], swB[NBT];
    #pragma unroll
    for (int bt = 0; bt < NBT; bt++) {
        int row = warp_n * WN + bt * 16 + ((lane >> 4) << 3) + (lane & 7);
        rB[bt]  = row * 256;
        swB[bt] = row & 7;
    }
    const int hB = (lane >> 3) & 1;

    // --- A stage registers (raw fp32 of one tile) ---
    float va[4][8];

    auto loadA = [&](int t) {
        int m0 = t << 7;
        #pragma unroll
        for (int i = 0; i < 4; i++) {
            int c   = tid + i * 512;
            int row = c >> 4;
            int c16 = c & 15;
            int gr  = m0 + row;
            if (gr < n) {
                float4 p0 = *reinterpret_cast<const float4*>(A + (size_t)gr * K + c16 * 8);
                float4 p1 = *reinterpret_cast<const float4*>(A + (size_t)gr * K + c16 * 8 + 4);
                va[i][0]=p0.x; va[i][1]=p0.y; va[i][2]=p0.z; va[i][3]=p0.w;
                va[i][4]=p1.x; va[i][5]=p1.y; va[i][6]=p1.z; va[i][7]=p1.w;
            } else {
                #pragma unroll
                for (int q = 0; q < 8; q++) va[i][q] = 0.0f;
            }
        }
    };

    auto stsA = [&]() {
        #pragma unroll
        for (int i = 0; i < 4; i++) {
            int c   = tid + i * 512;
            int row = c >> 4;
            int c16 = c & 15;
            struct alignas(16) BF8 { __nv_bfloat16 b[8]; } hh, ll;
            #pragma unroll
            for (int q = 0; q < 8; q++) {
                float x = va[i][q];
                if (RELU) x = fmaxf(x, 0.0f);
                __nv_bfloat16 h = __float2bfloat16(x);
                hh.b[q] = h;
                ll.b[q] = __float2bfloat16(x - __bfloat162float(h));
            }
            uint32_t off = (uint32_t)row * 256u + (((uint32_t)(c16 ^ (row & 7))) << 4);
            *reinterpret_cast<BF8*>(sAh + off) = hh;
            *reinterpret_cast<BF8*>(sAl + off) = ll;
        }
    };

    loadA(blockIdx.x);

    for (int t = blockIdx.x; t < ntiles; t += gridDim.x) {
        stsA();
        __syncthreads();

        float acc[2][NT][4];
        #pragma unroll
        for (int mt = 0; mt < 2; mt++)
            #pragma unroll
            for (int nt = 0; nt < NT; nt++)
                #pragma unroll
                for (int q = 0; q < 4; q++)
                    acc[mt][nt][q] = 0.0f;

        #pragma unroll
        for (int pass = 0; pass < 3; pass++) {
            const uint32_t Ab = (pass == 1) ? aAl : aAh;
            const uint32_t Bb = (pass == 2) ? aBl : aBh;
            #pragma unroll
            for (int s = 0; s < 8; s++) {
                uint32_t a[2][4];
                #pragma unroll
                for (int mt = 0; mt < 2; mt++)
                    ldsm4(a[mt], Ab + rA[mt] + (uint32_t)(((2 * s + hiA) ^ swA[mt]) << 4));
                uint32_t b[NBT][4];
                #pragma unroll
                for (int bt = 0; bt < NBT; bt++)
                    ldsm4(b[bt], Bb + rB[bt] + (uint32_t)(((2 * s + hB) ^ swB[bt]) << 4));
                #pragma unroll
                for (int mt = 0; mt < 2; mt++)
                    #pragma unroll
                    for (int nt = 0; nt < NT; nt++)
                        mma16816(acc[mt][nt], a[mt], &b[nt >> 1][(nt & 1) * 2]);
            }
        }
        __syncthreads();   // all ldsm done; A smem free for next tile

        // issue next tile's global loads early (overlap with epilogue stores)
        int tn = t + gridDim.x;
        if (tn < ntiles) loadA(tn);

        // epilogue for tile t
        int m0 = t << 7;
        #pragma unroll
        for (int mt = 0; mt < 2; mt++) {
            int gr0 = m0 + warp_m * 32 + mt * 16 + (lane >> 2);
            #pragma unroll
            for (int nt = 0; nt < NT; nt++) {
                int J = warp_n * WN + nt * 8 + (lane & 3) * 2;
                #pragma unroll
                for (int rr = 0; rr < 2; rr++) {
                    int gr = gr0 + rr * 8;
                    if (gr >= n) continue;
                    float c0 = acc[mt][nt][rr * 2 + 0];
                    float c1 = acc[mt][nt][rr * 2 + 1];
                    if (J < HC) {
                        if (J < RS) {
                            float2 o = make_float2(c0 + sBias[J], c1 + sBias[J + 1]);
                            *reinterpret_cast<float2*>(S + (size_t)gr * RS + J) = o;
                        }
                    } else {
                        int j2 = J - HC;
                        if (j2 < RS) {
                            *reinterpret_cast<float2*>(Y + (size_t)gr * RS + j2) =
                                make_float2(c0, c1);
                        }
                    }
                }
            }
        }
    }
}

// ---------------------------------------------------------------------------
// Gather aggregation: one warp per node, 4-way edge unroll.
// ---------------------------------------------------------------------------
template<int NV4, int RS>
__global__ __launch_bounds__(256) void agg_kernel(
    const float* __restrict__ Y, float* __restrict__ S,
    const int* __restrict__ csr, const int* __restrict__ off,
    const int* __restrict__ deg, const float* __restrict__ inv, int n)
{
    int w    = (blockIdx.x * blockDim.x + threadIdx.x) >> 5;
    int lane = threadIdx.x & 31;
    if (w >= n) return;
    if (lane >= NV4) return;

    int base = off[w];
    int dg   = deg[w];
    if (dg == 0) return;

    float4 a0 = make_float4(0.f, 0.f, 0.f, 0.f);
    float4 a1 = a0, a2 = a0, a3 = a0;

    int i = 0;
    for (; i + 3 < dg; i += 4) {
        int s0 = __ldg(&csr[base + i + 0]);
        int s1 = __ldg(&csr[base + i + 1]);
        int s2 = __ldg(&csr[base + i + 2]);
        int s3 = __ldg(&csr[base + i + 3]);
        float4 v0 = __ldg(reinterpret_cast<const float4*>(Y + (size_t)s0 * RS) + lane);
        float4 v1 = __ldg(reinterpret_cast<const float4*>(Y + (size_t)s1 * RS) + lane);
        float4 v2 = __ldg(reinterpret_cast<const float4*>(Y + (size_t)s2 * RS) + lane);
        float4 v3 = __ldg(reinterpret_cast<const float4*>(Y + (size_t)s3 * RS) + lane);
        a0.x += v0.x; a0.y += v0.y; a0.z += v0.z; a0.w += v0.w;
        a1.x += v1.x; a1.y += v1.y; a1.z += v1.z; a1.w += v1.w;
        a2.x += v2.x; a2.y += v2.y; a2.z += v2.z; a2.w += v2.w;
        a3.x += v3.x; a3.y += v3.y; a3.z += v3.z; a3.w += v3.w;
    }
    for (; i < dg; i++) {
        int s0 = __ldg(&csr[base + i]);
        float4 v0 = __ldg(reinterpret_cast<const float4*>(Y + (size_t)s0 * RS) + lane);
        a0.x += v0.x; a0.y += v0.y; a0.z += v0.z; a0.w += v0.w;
    }

    float iv = __ldg(&inv[w]);
    float4* sp = reinterpret_cast<float4*>(S + (size_t)w * RS) + lane;
    float4 cur = *sp;
    cur.x += iv * (a0.x + a1.x + a2.x + a3.x);
    cur.y += iv * (a0.y + a1.y + a2.y + a3.y);
    cur.z += iv * (a0.z + a1.z + a2.z + a3.z);
    cur.w += iv * (a0.w + a1.w + a2.w + a3.w);
    *sp = cur;
}

// ---------------------------------------------------------------------------
__global__ void copy_out_kernel(const float* __restrict__ S, float* __restrict__ out, int n) {
    int idx = blockIdx.x * blockDim.x + threadIdx.x;
    int total = n * 47;
    if (idx < total) {
        int r = idx / 47;
        int c = idx - r * 47;
        out[idx] = S[(size_t)r * 48 + c];
    }
}

// ---------------------------------------------------------------------------
extern "C" void kernel_launch(void* const* d_in, const int* in_sizes, int n_in,
                              void* d_out, int out_size)
{
    const float* x   = (const float*)d_in[0];
    const int*   src = (const int*)d_in[1];
    const int*   dst = (const int*)d_in[2];
    const float* ws0 = (const float*)d_in[3];
    const float* wn0 = (const float*)d_in[4];
    const float* b0  = (const float*)d_in[5];
    const float* ws1 = (const float*)d_in[6];
    const float* wn1 = (const float*)d_in[7];
    const float* b1  = (const float*)d_in[8];
    const float* ws2 = (const float*)d_in[9];
    const float* wn2 = (const float*)d_in[10];
    const float* b2  = (const float*)d_in[11];
    float* out = (float*)d_out;

    const int n = in_sizes[0] / 128;   // 100000
    const int e = in_sizes[1];         // 1600000

    float *SA, *SB, *Yb, *inv, *b0p, *b1p, *b2p;
    __nv_bfloat16 *B0, *B1, *B2;
    int *deg, *off, *cur, *csr, *bsum;
    cudaGetSymbolAddress((void**)&SA,   g_SA);
    cudaGetSymbolAddress((void**)&SB,   g_SB);
    cudaGetSymbolAddress((void**)&Yb,   g_Yb);
    cudaGetSymbolAddress((void**)&inv,  g_inv);
    cudaGetSymbolAddress((void**)&deg,  g_deg);
    cudaGetSymbolAddress((void**)&off,  g_off);
    cudaGetSymbolAddress((void**)&cur,  g_cur);
    cudaGetSymbolAddress((void**)&csr,  g_csr);
    cudaGetSymbolAddress((void**)&bsum, g_bsum);
    cudaGetSymbolAddress((void**)&B0,   g_B0);
    cudaGetSymbolAddress((void**)&B1,   g_B1);
    cudaGetSymbolAddress((void**)&B2,   g_B2);
    cudaGetSymbolAddress((void**)&b0p,  g_b0p);
    cudaGetSymbolAddress((void**)&b1p,  g_b1p);
    cudaGetSymbolAddress((void**)&b2p,  g_b2p);

    // dynamic smem: 64KB A + 2*NB*256 B + bias
    const int SMEM_BIG   = 65536 + 2 * 256 * 256 + 512;   // 197120
    const int SMEM_SMALL = 65536 + 2 * 128 * 256 + 512;   // 131584
    cudaFuncSetAttribute(gemm_mma_kernel<256, 128, false>,
                         cudaFuncAttributeMaxDynamicSharedMemorySize, SMEM_BIG);
    cudaFuncSetAttribute(gemm_mma_kernel<256, 128, true>,
                         cudaFuncAttributeMaxDynamicSharedMemorySize, SMEM_BIG);
    cudaFuncSetAttribute(gemm_mma_kernel<128, 48, true>,
                         cudaFuncAttributeMaxDynamicSharedMemorySize, SMEM_SMALL);

    const int ntiles  = (n + 127) / 128;   // 782
    const int PGRID   = 148;               // persistent: one CTA per SM
    const int ablocks = (n * 32 + 255) / 256;
    const int nb = (n + 1023) / 1024;

    // Harness pre-issues 2 launches; ncu -s 5 -c 1 profiles overall #6 = my #4.
    pack_all_kernel<<<(81920 + 255) / 256, 256>>>(
        ws0, wn0, b0, ws1, wn1, b1, ws2, wn2, b2,
        B0, B1, B2, b0p, b1p, b2p);                                   // my 1
    deg_zero_kernel<<<(n + 255) / 256, 256>>>(deg, n);                // my 2
    deg_count_kernel<<<(e + 255) / 256, 256>>>(deg, dst, e);          // my 3

    gemm_mma_kernel<256, 128, false><<<PGRID, 512, SMEM_BIG>>>(
        x, n, ntiles, B0, b0p, SA, Yb);                               // my 4 <- profiled

    scan1_kernel<<<nb, 1024>>>(deg, off, bsum, n);                    // my 5
    scan2_kernel<<<1, 1024>>>(bsum, nb);                              // my 6
    scan3_inv_kernel<<<(n + 255) / 256, 256>>>(off, cur, bsum, deg, inv, n);  // my 7
    csr_fill_kernel<<<(e + 255) / 256, 256>>>(src, dst, cur, csr, e);         // my 8

    agg_kernel<32, 128><<<ablocks, 256>>>(Yb, SA, csr, off, deg, inv, n);     // my 9

    gemm_mma_kernel<256, 128, true><<<PGRID, 512, SMEM_BIG>>>(
        SA, n, ntiles, B1, b1p, SB, Yb);                                      // my 10
    agg_kernel<32, 128><<<ablocks, 256>>>(Yb, SB, csr, off, deg, inv, n);     // my 11

    gemm_mma_kernel<128, 48, true><<<PGRID, 512, SMEM_SMALL>>>(
        SB, n, ntiles, B2, b2p, SA, Yb);                                      // my 12
    agg_kernel<12, 48><<<ablocks, 256>>>(Yb, SA, csr, off, deg, inv, n);      // my 13

    copy_out_kernel<<<(n * 47 + 255) / 256, 256>>>(SA, out, n);               // my 14
}

// round 8
// speedup vs baseline: 1.3736x; 1.1300x over previous
#include <cuda_runtime.h>
#include <cuda_bf16.h>
#include <cstdint>
#include <cstddef>

// ---------------------------------------------------------------------------
// GraphSAGE 3-layer forward, fp32 I/O, GB300 (sm_103a host, compute_103 PTX).
//   * transform-then-aggregate (aggregation is linear)
//   * GEMM: warp-level mma.sync bf16 (HMMA), hi/lo split (3 passes),
//     persistent CTAs, B resident in smem, cp.async double-buffered A tiles
//     (64 rows) so DRAM latency hides under the mma phase.
//   * per-call CSR build, gather aggregation (no feature atomics)
// ---------------------------------------------------------------------------

#define NMAX 100000
#define EMAX 1600000

__device__ float g_SA[(size_t)NMAX * 128];
__device__ float g_SB[(size_t)NMAX * 128];
__device__ float g_Yb[(size_t)NMAX * 128];
__device__ float g_inv[NMAX];
__device__ int   g_deg[NMAX];
__device__ int   g_off[NMAX];
__device__ int   g_cur[NMAX];
__device__ int   g_csr[EMAX];
__device__ int   g_bsum[1024];
// prepacked bf16 weight images (hi image then lo image, swizzled smem layout)
__device__ __nv_bfloat16 g_B0[2 * 256 * 128];
__device__ __nv_bfloat16 g_B1[2 * 256 * 128];
__device__ __nv_bfloat16 g_B2[2 * 128 * 128];
__device__ float g_b0p[128];
__device__ float g_b1p[128];
__device__ float g_b2p[64];

// ---------------------------------------------------------------------------
// PTX helpers
// ---------------------------------------------------------------------------
__device__ __forceinline__ uint32_t smem_u32(const void* p) {
    uint32_t a;
    asm("{ .reg .u64 t; cvta.to.shared.u64 t, %1; cvt.u32.u64 %0, t; }"
        : "=r"(a) : "l"(p));
    return a;
}

__device__ __forceinline__ void ldsm4(uint32_t* r, uint32_t addr) {
    asm volatile("ldmatrix.sync.aligned.m8n8.x4.shared.b16 {%0,%1,%2,%3}, [%4];"
        : "=r"(r[0]), "=r"(r[1]), "=r"(r[2]), "=r"(r[3]) : "r"(addr));
}

__device__ __forceinline__ void mma16816(float* c, const uint32_t* a, const uint32_t* b) {
    asm volatile(
        "mma.sync.aligned.m16n8k16.row.col.f32.bf16.bf16.f32 "
        "{%0,%1,%2,%3}, {%4,%5,%6,%7}, {%8,%9}, {%0,%1,%2,%3};"
        : "+f"(c[0]), "+f"(c[1]), "+f"(c[2]), "+f"(c[3])
        : "r"(a[0]), "r"(a[1]), "r"(a[2]), "r"(a[3]), "r"(b[0]), "r"(b[1]));
}

__device__ __forceinline__ void cpasync16(uint32_t dst, const void* src) {
    asm volatile("cp.async.cg.shared.global [%0], [%1], 16;"
                 :: "r"(dst), "l"(src) : "memory");
}
__device__ __forceinline__ void cpasync_commit() {
    asm volatile("cp.async.commit_group;" ::: "memory");
}
__device__ __forceinline__ void cpasync_wait0() {
    asm volatile("cp.async.wait_group 0;" ::: "memory");
}

// ---------------------------------------------------------------------------
// graph-structure kernels
// ---------------------------------------------------------------------------
__global__ void deg_zero_kernel(int* __restrict__ deg, int n) {
    int i = blockIdx.x * blockDim.x + threadIdx.x;
    if (i < n) deg[i] = 0;
}
__global__ void deg_count_kernel(int* __restrict__ deg, const int* __restrict__ dst, int e) {
    int i = blockIdx.x * blockDim.x + threadIdx.x;
    if (i < e) atomicAdd(&deg[dst[i]], 1);
}

__global__ __launch_bounds__(1024) void scan1_kernel(
    const int* __restrict__ deg, int* __restrict__ off, int* __restrict__ bsum, int n)
{
    __shared__ int sh[1024];
    int t = threadIdx.x;
    int i = blockIdx.x * 1024 + t;
    int v = (i < n) ? deg[i] : 0;
    sh[t] = v;
    __syncthreads();
    #pragma unroll
    for (int s = 1; s < 1024; s <<= 1) {
        int x = (t >= s) ? sh[t - s] : 0;
        __syncthreads();
        sh[t] += x;
        __syncthreads();
    }
    if (i < n) off[i] = sh[t] - v;
    if (t == 1023) bsum[blockIdx.x] = sh[t];
}

__global__ __launch_bounds__(1024) void scan2_kernel(int* __restrict__ bsum, int nb) {
    __shared__ int sh[1024];
    int t = threadIdx.x;
    int v = (t < nb) ? bsum[t] : 0;
    sh[t] = v;
    __syncthreads();
    #pragma unroll
    for (int s = 1; s < 1024; s <<= 1) {
        int x = (t >= s) ? sh[t - s] : 0;
        __syncthreads();
        sh[t] += x;
        __syncthreads();
    }
    if (t < nb) bsum[t] = sh[t] - v;
}

__global__ void scan3_inv_kernel(int* __restrict__ off, int* __restrict__ cur,
                                 const int* __restrict__ bsum,
                                 const int* __restrict__ deg,
                                 float* __restrict__ inv, int n) {
    int i = blockIdx.x * blockDim.x + threadIdx.x;
    if (i < n) {
        int o = off[i] + bsum[i >> 10];
        off[i] = o;
        cur[i] = o;
        int d = deg[i];
        inv[i] = 1.0f / (float)(d > 1 ? d : 1);
    }
}

__global__ void csr_fill_kernel(const int* __restrict__ src, const int* __restrict__ dst,
                                int* __restrict__ cur, int* __restrict__ csr, int e) {
    int i = blockIdx.x * blockDim.x + threadIdx.x;
    if (i < e) {
        int d = dst[i];
        int p = atomicAdd(&cur[d], 1);
        csr[p] = src[i];
    }
}

// ---------------------------------------------------------------------------
// weight prepack: bf16 hi/lo images in the smem ldmatrix layout.
//   byte = nrow*256 + (((k>>3) ^ (nrow&7)) << 4) + (k&7)*2
// hi image at [0, NB*128), lo at [NB*128, 2*NB*128) elements.
// ---------------------------------------------------------------------------
__device__ __forceinline__ void pack_one(__nv_bfloat16* img, int NB, int nrow, int k, float w) {
    __nv_bfloat16 h = __float2bfloat16(w);
    __nv_bfloat16 l = __float2bfloat16(w - __bfloat162float(h));
    uint32_t off = (uint32_t)nrow * 256u
                 + ((((uint32_t)k >> 3) ^ ((uint32_t)nrow & 7u)) << 4)
                 + ((uint32_t)k & 7u) * 2u;
    char* hi = reinterpret_cast<char*>(img);
    char* lo = reinterpret_cast<char*>(img + (size_t)NB * 128);
    *reinterpret_cast<__nv_bfloat16*>(hi + off) = h;
    *reinterpret_cast<__nv_bfloat16*>(lo + off) = l;
}

__global__ void pack_all_kernel(
    const float* __restrict__ ws0, const float* __restrict__ wn0, const float* __restrict__ b0,
    const float* __restrict__ ws1, const float* __restrict__ wn1, const float* __restrict__ b1,
    const float* __restrict__ ws2, const float* __restrict__ wn2, const float* __restrict__ b2,
    __nv_bfloat16* __restrict__ B0, __nv_bfloat16* __restrict__ B1, __nv_bfloat16* __restrict__ B2,
    float* __restrict__ b0p, float* __restrict__ b1p, float* __restrict__ b2p)
{
    int idx = blockIdx.x * blockDim.x + threadIdx.x;
    if (idx < 32768) {                       // layer 0: NB=256
        int nrow = idx >> 7, k = idx & 127;
        float w = (nrow < 128) ? ws0[k * 128 + nrow] : wn0[k * 128 + (nrow - 128)];
        pack_one(B0, 256, nrow, k, w);
    } else if (idx < 65536) {                // layer 1
        int t = idx - 32768;
        int nrow = t >> 7, k = t & 127;
        float w = (nrow < 128) ? ws1[k * 128 + nrow] : wn1[k * 128 + (nrow - 128)];
        pack_one(B1, 256, nrow, k, w);
    } else if (idx < 65536 + 16384) {        // layer 2: NB=128, WC=47 pad 64
        int t = idx - 65536;
        int nrow = t >> 7, k = t & 127;
        float w = 0.0f;
        if (nrow < 64) { if (nrow < 47) w = ws2[k * 47 + nrow]; }
        else           { int jj = nrow - 64; if (jj < 47) w = wn2[k * 47 + jj]; }
        pack_one(B2, 128, nrow, k, w);
    }
    if (idx < 128) { b0p[idx] = b0[idx]; b1p[idx] = b1[idx]; }
    if (idx < 64)  { b2p[idx] = (idx < 47) ? b2[idx] : 0.0f; }
}

// ---------------------------------------------------------------------------
// PERSISTENT HMMA GEMM, cp.async pipelined.
// grid = #SMs, 512 threads, B + bias resident. 64-row M-tiles:
//   stage0/stage1 (fp32, cp.async targets), Ah/Al (bf16 split), B hi/lo.
// Loop: wait cp.async -> convert (per-thread own data, no sync) ->
//       issue cp.async(t+1) -> sync -> mma (3 passes x 8 k16) -> sync ->
//       epilogue stores.
// Warps 2(m) x 8(n); warp tile m32 x (NB/8).
//   D[64, NB] = relu?(A)[64,128] @ W^T ; cols [0,NB/2)->S(+bias), rest->Y.
// smem: 0 stage0 | 32768 stage1 | 65536 Ah | 81920 Al | 98304 B | +2*NB*256 bias
// ---------------------------------------------------------------------------
template<int NB, int RS, bool RELU>
__global__ void __launch_bounds__(512, 1) gemm_mma_kernel(
    const float* __restrict__ A, int n, int ntiles,
    const __nv_bfloat16* __restrict__ Bimg, const float* __restrict__ bias,
    float* __restrict__ S, float* __restrict__ Y)
{
    constexpr int WN  = NB / 8;     // warp n-extent: 32 or 16
    constexpr int NBT = (WN / 16 > 0) ? WN / 16 : 1;  // B ldsm tiles: 2 or 1
    constexpr int NT  = WN / 8;     // n8 mma tiles per warp: 4 or 2
    constexpr int HC  = NB / 2;

    extern __shared__ char smem[];
    char*  sB    = smem + 98304;
    float* sBias = reinterpret_cast<float*>(smem + 98304 + 2 * NB * 256);

    const int tid    = threadIdx.x;
    const int wid    = tid >> 5;
    const int lane   = tid & 31;
    const int warp_m = wid & 1;     // 0..1
    const int warp_n = wid >> 1;    // 0..7

    // --- B + bias: resident copy, once ---
    {
        const uint4* src = reinterpret_cast<const uint4*>(Bimg);
        uint4* dst = reinterpret_cast<uint4*>(sB);
        constexpr int CNT = NB * 32;        // 2*NB*256 / 16
        #pragma unroll
        for (int i = 0; i < CNT / 512; i++)
            dst[tid + i * 512] = src[tid + i * 512];
        if (tid < HC) sBias[tid] = bias[tid];
    }

    const uint32_t sb  = smem_u32(smem);
    const uint32_t aAh = sb + 65536;
    const uint32_t aAl = sb + 81920;
    const uint32_t aBh = sb + 98304;
    const uint32_t aBl = aBh + NB * 256;

    const int arow = tid >> 3;          // 0..63 (tile row this thread stages)
    const int acol = (tid & 7) * 16;    // float column base (16 floats/thread)

    // --- cp.async stage: 16 fp32 per thread, 4x 16B chunks ---
    auto loadA_async = [&](int t, int buf) {
        int gr = (t << 6) + arow;
        if (gr > n - 1) gr = n - 1;     // clamp: garbage rows never stored
        const float* src = A + (size_t)gr * 128 + acol;
        uint32_t dst = sb + buf * 32768 + arow * 512 + acol * 4;
        #pragma unroll
        for (int j = 0; j < 4; j++)
            cpasync16(dst + j * 16, src + j * 4);
        cpasync_commit();
    };

    // --- convert own staged fp32 -> bf16 hi/lo swizzled (no sync needed) ---
    auto convert = [&](int buf) {
        const float4* sp = reinterpret_cast<const float4*>(
            smem + buf * 32768 + arow * 512 + acol * 4);
        float4 f0 = sp[0], f1 = sp[1], f2 = sp[2], f3 = sp[3];
        float v[16] = {f0.x, f0.y, f0.z, f0.w, f1.x, f1.y, f1.z, f1.w,
                       f2.x, f2.y, f2.z, f2.w, f3.x, f3.y, f3.z, f3.w};
        #pragma unroll
        for (int h = 0; h < 2; h++) {
            struct alignas(16) BF8 { __nv_bfloat16 b[8]; } hh, ll;
            #pragma unroll
            for (int q = 0; q < 8; q++) {
                float x = v[h * 8 + q];
                if (RELU) x = fmaxf(x, 0.0f);
                __nv_bfloat16 hb = __float2bfloat16(x);
                hh.b[q] = hb;
                ll.b[q] = __float2bfloat16(x - __bfloat162float(hb));
            }
            int c16 = (tid & 7) * 2 + h;
            uint32_t off = (uint32_t)arow * 256u
                         + (uint32_t)((c16 ^ (arow & 7)) << 4);
            *reinterpret_cast<BF8*>(smem + 65536 + off) = hh;
            *reinterpret_cast<BF8*>(smem + 81920 + off) = ll;
        }
    };

    // --- ldmatrix addressing (fixed per thread) ---
    int rA[2], swA[2];
    #pragma unroll
    for (int mt = 0; mt < 2; mt++) {
        int row = warp_m * 32 + mt * 16 + (lane & 15);
        rA[mt]  = row * 256;
        swA[mt] = row & 7;
    }
    const int hiA = lane >> 4;
    int rB[NBT], swB[NBT];
    #pragma unroll
    for (int bt = 0; bt < NBT; bt++) {
        int row = warp_n * WN + bt * 16 + ((lane >> 4) << 3) + (lane & 7);
        rB[bt]  = row * 256;
        swB[bt] = row & 7;
    }
    const int hB = (lane >> 3) & 1;

    int buf = 0;
    loadA_async(blockIdx.x, 0);

    for (int t = blockIdx.x; t < ntiles; t += gridDim.x) {
        cpasync_wait0();
        convert(buf);
        int tn = t + gridDim.x;
        if (tn < ntiles) loadA_async(tn, buf ^ 1);
        __syncthreads();                // Ah/Al (and first-pass B) ready

        float acc[2][NT][4];
        #pragma unroll
        for (int mt = 0; mt < 2; mt++)
            #pragma unroll
            for (int nt = 0; nt < NT; nt++)
                #pragma unroll
                for (int q = 0; q < 4; q++)
                    acc[mt][nt][q] = 0.0f;

        #pragma unroll
        for (int pass = 0; pass < 3; pass++) {
            const uint32_t Ab = (pass == 1) ? aAl : aAh;
            const uint32_t Bb = (pass == 2) ? aBl : aBh;
            #pragma unroll
            for (int s = 0; s < 8; s++) {
                uint32_t a[2][4];
                #pragma unroll
                for (int mt = 0; mt < 2; mt++)
                    ldsm4(a[mt], Ab + rA[mt] + (uint32_t)(((2 * s + hiA) ^ swA[mt]) << 4));
                uint32_t b[NBT][4];
                #pragma unroll
                for (int bt = 0; bt < NBT; bt++)
                    ldsm4(b[bt], Bb + rB[bt] + (uint32_t)(((2 * s + hB) ^ swB[bt]) << 4));
                #pragma unroll
                for (int mt = 0; mt < 2; mt++)
                    #pragma unroll
                    for (int nt = 0; nt < NT; nt++)
                        mma16816(acc[mt][nt], a[mt], &b[nt >> 1][(nt & 1) * 2]);
            }
        }
        __syncthreads();                // ldsm done; Ah/Al free for next tile

        // epilogue for tile t (overlaps next tile's cp.async in flight)
        int m0 = t << 6;
        #pragma unroll
        for (int mt = 0; mt < 2; mt++) {
            int gr0 = m0 + warp_m * 32 + mt * 16 + (lane >> 2);
            #pragma unroll
            for (int nt = 0; nt < NT; nt++) {
                int J = warp_n * WN + nt * 8 + (lane & 3) * 2;
                #pragma unroll
                for (int rr = 0; rr < 2; rr++) {
                    int gr = gr0 + rr * 8;
                    if (gr >= n) continue;
                    float c0 = acc[mt][nt][rr * 2 + 0];
                    float c1 = acc[mt][nt][rr * 2 + 1];
                    if (J < HC) {
                        if (J < RS) {
                            float2 o = make_float2(c0 + sBias[J], c1 + sBias[J + 1]);
                            *reinterpret_cast<float2*>(S + (size_t)gr * RS + J) = o;
                        }
                    } else {
                        int j2 = J - HC;
                        if (j2 < RS) {
                            *reinterpret_cast<float2*>(Y + (size_t)gr * RS + j2) =
                                make_float2(c0, c1);
                        }
                    }
                }
            }
        }
        buf ^= 1;
    }
}

// ---------------------------------------------------------------------------
// Gather aggregation: one warp per node, 4-way edge unroll.
// ---------------------------------------------------------------------------
template<int NV4, int RS>
__global__ __launch_bounds__(256) void agg_kernel(
    const float* __restrict__ Y, float* __restrict__ S,
    const int* __restrict__ csr, const int* __restrict__ off,
    const int* __restrict__ deg, const float* __restrict__ inv, int n)
{
    int w    = (blockIdx.x * blockDim.x + threadIdx.x) >> 5;
    int lane = threadIdx.x & 31;
    if (w >= n) return;
    if (lane >= NV4) return;

    int base = off[w];
    int dg   = deg[w];
    if (dg == 0) return;

    float4 a0 = make_float4(0.f, 0.f, 0.f, 0.f);
    float4 a1 = a0, a2 = a0, a3 = a0;

    int i = 0;
    for (; i + 3 < dg; i += 4) {
        int s0 = __ldg(&csr[base + i + 0]);
        int s1 = __ldg(&csr[base + i + 1]);
        int s2 = __ldg(&csr[base + i + 2]);
        int s3 = __ldg(&csr[base + i + 3]);
        float4 v0 = __ldg(reinterpret_cast<const float4*>(Y + (size_t)s0 * RS) + lane);
        float4 v1 = __ldg(reinterpret_cast<const float4*>(Y + (size_t)s1 * RS) + lane);
        float4 v2 = __ldg(reinterpret_cast<const float4*>(Y + (size_t)s2 * RS) + lane);
        float4 v3 = __ldg(reinterpret_cast<const float4*>(Y + (size_t)s3 * RS) + lane);
        a0.x += v0.x; a0.y += v0.y; a0.z += v0.z; a0.w += v0.w;
        a1.x += v1.x; a1.y += v1.y; a1.z += v1.z; a1.w += v1.w;
        a2.x += v2.x; a2.y += v2.y; a2.z += v2.z; a2.w += v2.w;
        a3.x += v3.x; a3.y += v3.y; a3.z += v3.z; a3.w += v3.w;
    }
    for (; i < dg; i++) {
        int s0 = __ldg(&csr[base + i]);
        float4 v0 = __ldg(reinterpret_cast<const float4*>(Y + (size_t)s0 * RS) + lane);
        a0.x += v0.x; a0.y += v0.y; a0.z += v0.z; a0.w += v0.w;
    }

    float iv = __ldg(&inv[w]);
    float4* sp = reinterpret_cast<float4*>(S + (size_t)w * RS) + lane;
    float4 cur = *sp;
    cur.x += iv * (a0.x + a1.x + a2.x + a3.x);
    cur.y += iv * (a0.y + a1.y + a2.y + a3.y);
    cur.z += iv * (a0.z + a1.z + a2.z + a3.z);
    cur.w += iv * (a0.w + a1.w + a2.w + a3.w);
    *sp = cur;
}

// ---------------------------------------------------------------------------
__global__ void copy_out_kernel(const float* __restrict__ S, float* __restrict__ out, int n) {
    int idx = blockIdx.x * blockDim.x + threadIdx.x;
    int total = n * 47;
    if (idx < total) {
        int r = idx / 47;
        int c = idx - r * 47;
        out[idx] = S[(size_t)r * 48 + c];
    }
}

// ---------------------------------------------------------------------------
extern "C" void kernel_launch(void* const* d_in, const int* in_sizes, int n_in,
                              void* d_out, int out_size)
{
    const float* x   = (const float*)d_in[0];
    const int*   src = (const int*)d_in[1];
    const int*   dst = (const int*)d_in[2];
    const float* ws0 = (const float*)d_in[3];
    const float* wn0 = (const float*)d_in[4];
    const float* b0  = (const float*)d_in[5];
    const float* ws1 = (const float*)d_in[6];
    const float* wn1 = (const float*)d_in[7];
    const float* b1  = (const float*)d_in[8];
    const float* ws2 = (const float*)d_in[9];
    const float* wn2 = (const float*)d_in[10];
    const float* b2  = (const float*)d_in[11];
    float* out = (float*)d_out;

    const int n = in_sizes[0] / 128;   // 100000
    const int e = in_sizes[1];         // 1600000

    float *SA, *SB, *Yb, *inv, *b0p, *b1p, *b2p;
    __nv_bfloat16 *B0, *B1, *B2;
    int *deg, *off, *cur, *csr, *bsum;
    cudaGetSymbolAddress((void**)&SA,   g_SA);
    cudaGetSymbolAddress((void**)&SB,   g_SB);
    cudaGetSymbolAddress((void**)&Yb,   g_Yb);
    cudaGetSymbolAddress((void**)&inv,  g_inv);
    cudaGetSymbolAddress((void**)&deg,  g_deg);
    cudaGetSymbolAddress((void**)&off,  g_off);
    cudaGetSymbolAddress((void**)&cur,  g_cur);
    cudaGetSymbolAddress((void**)&csr,  g_csr);
    cudaGetSymbolAddress((void**)&bsum, g_bsum);
    cudaGetSymbolAddress((void**)&B0,   g_B0);
    cudaGetSymbolAddress((void**)&B1,   g_B1);
    cudaGetSymbolAddress((void**)&B2,   g_B2);
    cudaGetSymbolAddress((void**)&b0p,  g_b0p);
    cudaGetSymbolAddress((void**)&b1p,  g_b1p);
    cudaGetSymbolAddress((void**)&b2p,  g_b2p);

    // dynamic smem: 64KB stage + 32KB Ah/Al + 2*NB*256 B + bias
    const int SMEM_BIG   = 98304 + 2 * 256 * 256 + 512;   // 229888
    const int SMEM_SMALL = 98304 + 2 * 128 * 256 + 512;   // 164352
    cudaFuncSetAttribute(gemm_mma_kernel<256, 128, false>,
                         cudaFuncAttributeMaxDynamicSharedMemorySize, SMEM_BIG);
    cudaFuncSetAttribute(gemm_mma_kernel<256, 128, true>,
                         cudaFuncAttributeMaxDynamicSharedMemorySize, SMEM_BIG);
    cudaFuncSetAttribute(gemm_mma_kernel<128, 48, true>,
                         cudaFuncAttributeMaxDynamicSharedMemorySize, SMEM_SMALL);

    const int ntiles  = (n + 63) / 64;     // 1563 (64-row tiles)
    const int PGRID   = 148;               // persistent: one CTA per SM
    const int ablocks = (n * 32 + 255) / 256;
    const int nb = (n + 1023) / 1024;

    // Harness pre-issues 2 launches; ncu -s 5 -c 1 profiles overall #6 = my #4.
    pack_all_kernel<<<(81920 + 255) / 256, 256>>>(
        ws0, wn0, b0, ws1, wn1, b1, ws2, wn2, b2,
        B0, B1, B2, b0p, b1p, b2p);                                   // my 1
    deg_zero_kernel<<<(n + 255) / 256, 256>>>(deg, n);                // my 2
    deg_count_kernel<<<(e + 255) / 256, 256>>>(deg, dst, e);          // my 3

    gemm_mma_kernel<256, 128, false><<<PGRID, 512, SMEM_BIG>>>(
        x, n, ntiles, B0, b0p, SA, Yb);                               // my 4 <- profiled

    scan1_kernel<<<nb, 1024>>>(deg, off, bsum, n);                    // my 5
    scan2_kernel<<<1, 1024>>>(bsum, nb);                              // my 6
    scan3_inv_kernel<<<(n + 255) / 256, 256>>>(off, cur, bsum, deg, inv, n);  // my 7
    csr_fill_kernel<<<(e + 255) / 256, 256>>>(src, dst, cur, csr, e);         // my 8

    agg_kernel<32, 128><<<ablocks, 256>>>(Yb, SA, csr, off, deg, inv, n);     // my 9

    gemm_mma_kernel<256, 128, true><<<PGRID, 512, SMEM_BIG>>>(
        SA, n, ntiles, B1, b1p, SB, Yb);                                      // my 10
    agg_kernel<32, 128><<<ablocks, 256>>>(Yb, SB, csr, off, deg, inv, n);     // my 11

    gemm_mma_kernel<128, 48, true><<<PGRID, 512, SMEM_SMALL>>>(
        SB, n, ntiles, B2, b2p, SA, Yb);                                      // my 12
    agg_kernel<12, 48><<<ablocks, 256>>>(Yb, SA, csr, off, deg, inv, n);      // my 13

    copy_out_kernel<<<(n * 47 + 255) / 256, 256>>>(SA, out, n);               // my 14
}

// round 9
// speedup vs baseline: 1.5630x; 1.1379x over previous
#include <cuda_runtime.h>
#include <cuda_bf16.h>
#include <cstdint>
#include <cstddef>

// ---------------------------------------------------------------------------
// GraphSAGE 3-layer forward, fp32 I/O, GB300 (sm_103a host, compute_103 PTX).
//   * transform-then-aggregate (aggregation is linear)
//   * GEMM: warp-level mma.sync bf16 (HMMA), hi/lo split, persistent CTAs,
//     B resident in smem, cp.async double-buffered 64-row A tiles,
//     FRAGMENT REUSE: Ah/Al/Bh/Bl loaded once per k-step, 3 mma combos each
//     (cuts LDSM crossbar traffic 33%).
//   * per-call CSR build, gather aggregation (no feature atomics)
// ---------------------------------------------------------------------------

#define NMAX 100000
#define EMAX 1600000

__device__ float g_SA[(size_t)NMAX * 128];
__device__ float g_SB[(size_t)NMAX * 128];
__device__ float g_Yb[(size_t)NMAX * 128];
__device__ float g_inv[NMAX];
__device__ int   g_deg[NMAX];
__device__ int   g_off[NMAX];
__device__ int   g_cur[NMAX];
__device__ int   g_csr[EMAX];
__device__ int   g_bsum[1024];
// prepacked bf16 weight images (hi image then lo image, swizzled smem layout)
__device__ __nv_bfloat16 g_B0[2 * 256 * 128];
__device__ __nv_bfloat16 g_B1[2 * 256 * 128];
__device__ __nv_bfloat16 g_B2[2 * 128 * 128];
__device__ float g_b0p[128];
__device__ float g_b1p[128];
__device__ float g_b2p[64];

// ---------------------------------------------------------------------------
// PTX helpers
// ---------------------------------------------------------------------------
__device__ __forceinline__ uint32_t smem_u32(const void* p) {
    uint32_t a;
    asm("{ .reg .u64 t; cvta.to.shared.u64 t, %1; cvt.u32.u64 %0, t; }"
        : "=r"(a) : "l"(p));
    return a;
}

__device__ __forceinline__ void ldsm4(uint32_t* r, uint32_t addr) {
    asm volatile("ldmatrix.sync.aligned.m8n8.x4.shared.b16 {%0,%1,%2,%3}, [%4];"
        : "=r"(r[0]), "=r"(r[1]), "=r"(r[2]), "=r"(r[3]) : "r"(addr));
}

__device__ __forceinline__ void mma16816(float* c, const uint32_t* a, const uint32_t* b) {
    asm volatile(
        "mma.sync.aligned.m16n8k16.row.col.f32.bf16.bf16.f32 "
        "{%0,%1,%2,%3}, {%4,%5,%6,%7}, {%8,%9}, {%0,%1,%2,%3};"
        : "+f"(c[0]), "+f"(c[1]), "+f"(c[2]), "+f"(c[3])
        : "r"(a[0]), "r"(a[1]), "r"(a[2]), "r"(a[3]), "r"(b[0]), "r"(b[1]));
}

__device__ __forceinline__ void cpasync16(uint32_t dst, const void* src) {
    asm volatile("cp.async.cg.shared.global [%0], [%1], 16;"
                 :: "r"(dst), "l"(src) : "memory");
}
__device__ __forceinline__ void cpasync_commit() {
    asm volatile("cp.async.commit_group;" ::: "memory");
}
__device__ __forceinline__ void cpasync_wait0() {
    asm volatile("cp.async.wait_group 0;" ::: "memory");
}

// ---------------------------------------------------------------------------
// graph-structure kernels
// ---------------------------------------------------------------------------
__global__ void deg_zero_kernel(int* __restrict__ deg, int n) {
    int i = blockIdx.x * blockDim.x + threadIdx.x;
    if (i < n) deg[i] = 0;
}
__global__ void deg_count_kernel(int* __restrict__ deg, const int* __restrict__ dst, int e) {
    int i = blockIdx.x * blockDim.x + threadIdx.x;
    if (i < e) atomicAdd(&deg[dst[i]], 1);
}

__global__ __launch_bounds__(1024) void scan1_kernel(
    const int* __restrict__ deg, int* __restrict__ off, int* __restrict__ bsum, int n)
{
    __shared__ int sh[1024];
    int t = threadIdx.x;
    int i = blockIdx.x * 1024 + t;
    int v = (i < n) ? deg[i] : 0;
    sh[t] = v;
    __syncthreads();
    #pragma unroll
    for (int s = 1; s < 1024; s <<= 1) {
        int x = (t >= s) ? sh[t - s] : 0;
        __syncthreads();
        sh[t] += x;
        __syncthreads();
    }
    if (i < n) off[i] = sh[t] - v;
    if (t == 1023) bsum[blockIdx.x] = sh[t];
}

__global__ __launch_bounds__(1024) void scan2_kernel(int* __restrict__ bsum, int nb) {
    __shared__ int sh[1024];
    int t = threadIdx.x;
    int v = (t < nb) ? bsum[t] : 0;
    sh[t] = v;
    __syncthreads();
    #pragma unroll
    for (int s = 1; s < 1024; s <<= 1) {
        int x = (t >= s) ? sh[t - s] : 0;
        __syncthreads();
        sh[t] += x;
        __syncthreads();
    }
    if (t < nb) bsum[t] = sh[t] - v;
}

__global__ void scan3_inv_kernel(int* __restrict__ off, int* __restrict__ cur,
                                 const int* __restrict__ bsum,
                                 const int* __restrict__ deg,
                                 float* __restrict__ inv, int n) {
    int i = blockIdx.x * blockDim.x + threadIdx.x;
    if (i < n) {
        int o = off[i] + bsum[i >> 10];
        off[i] = o;
        cur[i] = o;
        int d = deg[i];
        inv[i] = 1.0f / (float)(d > 1 ? d : 1);
    }
}

__global__ void csr_fill_kernel(const int* __restrict__ src, const int* __restrict__ dst,
                                int* __restrict__ cur, int* __restrict__ csr, int e) {
    int i = blockIdx.x * blockDim.x + threadIdx.x;
    if (i < e) {
        int d = dst[i];
        int p = atomicAdd(&cur[d], 1);
        csr[p] = src[i];
    }
}

// ---------------------------------------------------------------------------
// weight prepack: bf16 hi/lo images in the smem ldmatrix layout.
//   byte = nrow*256 + (((k>>3) ^ (nrow&7)) << 4) + (k&7)*2
// ---------------------------------------------------------------------------
__device__ __forceinline__ void pack_one(__nv_bfloat16* img, int NB, int nrow, int k, float w) {
    __nv_bfloat16 h = __float2bfloat16(w);
    __nv_bfloat16 l = __float2bfloat16(w - __bfloat162float(h));
    uint32_t off = (uint32_t)nrow * 256u
                 + ((((uint32_t)k >> 3) ^ ((uint32_t)nrow & 7u)) << 4)
                 + ((uint32_t)k & 7u) * 2u;
    char* hi = reinterpret_cast<char*>(img);
    char* lo = reinterpret_cast<char*>(img + (size_t)NB * 128);
    *reinterpret_cast<__nv_bfloat16*>(hi + off) = h;
    *reinterpret_cast<__nv_bfloat16*>(lo + off) = l;
}

__global__ void pack_all_kernel(
    const float* __restrict__ ws0, const float* __restrict__ wn0, const float* __restrict__ b0,
    const float* __restrict__ ws1, const float* __restrict__ wn1, const float* __restrict__ b1,
    const float* __restrict__ ws2, const float* __restrict__ wn2, const float* __restrict__ b2,
    __nv_bfloat16* __restrict__ B0, __nv_bfloat16* __restrict__ B1, __nv_bfloat16* __restrict__ B2,
    float* __restrict__ b0p, float* __restrict__ b1p, float* __restrict__ b2p)
{
    int idx = blockIdx.x * blockDim.x + threadIdx.x;
    if (idx < 32768) {                       // layer 0: NB=256
        int nrow = idx >> 7, k = idx & 127;
        float w = (nrow < 128) ? ws0[k * 128 + nrow] : wn0[k * 128 + (nrow - 128)];
        pack_one(B0, 256, nrow, k, w);
    } else if (idx < 65536) {                // layer 1
        int t = idx - 32768;
        int nrow = t >> 7, k = t & 127;
        float w = (nrow < 128) ? ws1[k * 128 + nrow] : wn1[k * 128 + (nrow - 128)];
        pack_one(B1, 256, nrow, k, w);
    } else if (idx < 65536 + 16384) {        // layer 2: NB=128, WC=47 pad 64
        int t = idx - 65536;
        int nrow = t >> 7, k = t & 127;
        float w = 0.0f;
        if (nrow < 64) { if (nrow < 47) w = ws2[k * 47 + nrow]; }
        else           { int jj = nrow - 64; if (jj < 47) w = wn2[k * 47 + jj]; }
        pack_one(B2, 128, nrow, k, w);
    }
    if (idx < 128) { b0p[idx] = b0[idx]; b1p[idx] = b1[idx]; }
    if (idx < 64)  { b2p[idx] = (idx < 47) ? b2[idx] : 0.0f; }
}

// ---------------------------------------------------------------------------
// PERSISTENT HMMA GEMM, cp.async pipelined, fragment-reuse mma loop.
// grid = #SMs, 512 threads, B + bias resident. 64-row M-tiles.
// Loop: wait cp.async -> convert -> issue cp.async(t+1) -> sync ->
//       for each k16 step: ldsm Ah,Al,Bh,Bl once -> 3 mma combos -> sync ->
//       epilogue stores.
// Warps 2(m) x 8(n); warp tile m32 x (NB/8).
// smem: 0 stage0 | 32768 stage1 | 65536 Ah | 81920 Al | 98304 B | +2*NB*256 bias
// ---------------------------------------------------------------------------
template<int NB, int RS, bool RELU>
__global__ void __launch_bounds__(512, 1) gemm_mma_kernel(
    const float* __restrict__ A, int n, int ntiles,
    const __nv_bfloat16* __restrict__ Bimg, const float* __restrict__ bias,
    float* __restrict__ S, float* __restrict__ Y)
{
    constexpr int WN  = NB / 8;     // warp n-extent: 32 or 16
    constexpr int NBT = (WN / 16 > 0) ? WN / 16 : 1;  // B ldsm tiles: 2 or 1
    constexpr int NT  = WN / 8;     // n8 mma tiles per warp: 4 or 2
    constexpr int HC  = NB / 2;

    extern __shared__ char smem[];
    char*  sB    = smem + 98304;
    float* sBias = reinterpret_cast<float*>(smem + 98304 + 2 * NB * 256);

    const int tid    = threadIdx.x;
    const int wid    = tid >> 5;
    const int lane   = tid & 31;
    const int warp_m = wid & 1;     // 0..1
    const int warp_n = wid >> 1;    // 0..7

    // --- B + bias: resident copy, once ---
    {
        const uint4* src = reinterpret_cast<const uint4*>(Bimg);
        uint4* dst = reinterpret_cast<uint4*>(sB);
        constexpr int CNT = NB * 32;        // 2*NB*256 / 16
        #pragma unroll
        for (int i = 0; i < CNT / 512; i++)
            dst[tid + i * 512] = src[tid + i * 512];
        if (tid < HC) sBias[tid] = bias[tid];
    }

    const uint32_t sb  = smem_u32(smem);
    const uint32_t aAh = sb + 65536;
    const uint32_t aAl = sb + 81920;
    const uint32_t aBh = sb + 98304;
    const uint32_t aBl = aBh + NB * 256;

    const int arow = tid >> 3;          // 0..63
    const int acol = (tid & 7) * 16;

    auto loadA_async = [&](int t, int buf) {
        int gr = (t << 6) + arow;
        if (gr > n - 1) gr = n - 1;     // clamp: garbage rows never stored
        const float* src = A + (size_t)gr * 128 + acol;
        uint32_t dst = sb + buf * 32768 + arow * 512 + acol * 4;
        #pragma unroll
        for (int j = 0; j < 4; j++)
            cpasync16(dst + j * 16, src + j * 4);
        cpasync_commit();
    };

    auto convert = [&](int buf) {
        const float4* sp = reinterpret_cast<const float4*>(
            smem + buf * 32768 + arow * 512 + acol * 4);
        float4 f0 = sp[0], f1 = sp[1], f2 = sp[2], f3 = sp[3];
        float v[16] = {f0.x, f0.y, f0.z, f0.w, f1.x, f1.y, f1.z, f1.w,
                       f2.x, f2.y, f2.z, f2.w, f3.x, f3.y, f3.z, f3.w};
        #pragma unroll
        for (int h = 0; h < 2; h++) {
            struct alignas(16) BF8 { __nv_bfloat16 b[8]; } hh, ll;
            #pragma unroll
            for (int q = 0; q < 8; q++) {
                float x = v[h * 8 + q];
                if (RELU) x = fmaxf(x, 0.0f);
                __nv_bfloat16 hb = __float2bfloat16(x);
                hh.b[q] = hb;
                ll.b[q] = __float2bfloat16(x - __bfloat162float(hb));
            }
            int c16 = (tid & 7) * 2 + h;
            uint32_t off = (uint32_t)arow * 256u
                         + (uint32_t)((c16 ^ (arow & 7)) << 4);
            *reinterpret_cast<BF8*>(smem + 65536 + off) = hh;
            *reinterpret_cast<BF8*>(smem + 81920 + off) = ll;
        }
    };

    // --- ldmatrix addressing (fixed per thread) ---
    int rA[2], swA[2];
    #pragma unroll
    for (int mt = 0; mt < 2; mt++) {
        int row = warp_m * 32 + mt * 16 + (lane & 15);
        rA[mt]  = row * 256;
        swA[mt] = row & 7;
    }
    const int hiA = lane >> 4;
    int rB[NBT], swB[NBT];
    #pragma unroll
    for (int bt = 0; bt < NBT; bt++) {
        int row = warp_n * WN + bt * 16 + ((lane >> 4) << 3) + (lane & 7);
        rB[bt]  = row * 256;
        swB[bt] = row & 7;
    }
    const int hB = (lane >> 3) & 1;

    int buf = 0;
    loadA_async(blockIdx.x, 0);

    for (int t = blockIdx.x; t < ntiles; t += gridDim.x) {
        cpasync_wait0();
        convert(buf);
        int tn = t + gridDim.x;
        if (tn < ntiles) loadA_async(tn, buf ^ 1);
        __syncthreads();                // Ah/Al ready

        float acc[2][NT][4];
        #pragma unroll
        for (int mt = 0; mt < 2; mt++)
            #pragma unroll
            for (int nt = 0; nt < NT; nt++)
                #pragma unroll
                for (int q = 0; q < 4; q++)
                    acc[mt][nt][q] = 0.0f;

        // fragment-reuse loop: one ldsm batch per k-step, 3 mma combos
        #pragma unroll
        for (int s = 0; s < 8; s++) {
            uint32_t ah[2][4], al[2][4];
            #pragma unroll
            for (int mt = 0; mt < 2; mt++) {
                uint32_t ofsA = (uint32_t)(((2 * s + hiA) ^ swA[mt]) << 4);
                ldsm4(ah[mt], aAh + rA[mt] + ofsA);
                ldsm4(al[mt], aAl + rA[mt] + ofsA);
            }
            uint32_t bh[NBT][4], bl[NBT][4];
            #pragma unroll
            for (int bt = 0; bt < NBT; bt++) {
                uint32_t ofsB = (uint32_t)(((2 * s + hB) ^ swB[bt]) << 4);
                ldsm4(bh[bt], aBh + rB[bt] + ofsB);
                ldsm4(bl[bt], aBl + rB[bt] + ofsB);
            }
            #pragma unroll
            for (int mt = 0; mt < 2; mt++)
                #pragma unroll
                for (int nt = 0; nt < NT; nt++) {
                    const uint32_t* bhp = &bh[nt >> 1][(nt & 1) * 2];
                    const uint32_t* blp = &bl[nt >> 1][(nt & 1) * 2];
                    mma16816(acc[mt][nt], ah[mt], bhp);   // Ah*Bh
                    mma16816(acc[mt][nt], al[mt], bhp);   // Al*Bh
                    mma16816(acc[mt][nt], ah[mt], blp);   // Ah*Bl
                }
        }
        __syncthreads();                // ldsm done; Ah/Al free for next tile

        // epilogue for tile t
        int m0 = t << 6;
        #pragma unroll
        for (int mt = 0; mt < 2; mt++) {
            int gr0 = m0 + warp_m * 32 + mt * 16 + (lane >> 2);
            #pragma unroll
            for (int nt = 0; nt < NT; nt++) {
                int J = warp_n * WN + nt * 8 + (lane & 3) * 2;
                #pragma unroll
                for (int rr = 0; rr < 2; rr++) {
                    int gr = gr0 + rr * 8;
                    if (gr >= n) continue;
                    float c0 = acc[mt][nt][rr * 2 + 0];
                    float c1 = acc[mt][nt][rr * 2 + 1];
                    if (J < HC) {
                        if (J < RS) {
                            float2 o = make_float2(c0 + sBias[J], c1 + sBias[J + 1]);
                            *reinterpret_cast<float2*>(S + (size_t)gr * RS + J) = o;
                        }
                    } else {
                        int j2 = J - HC;
                        if (j2 < RS) {
                            *reinterpret_cast<float2*>(Y + (size_t)gr * RS + j2) =
                                make_float2(c0, c1);
                        }
                    }
                }
            }
        }
        buf ^= 1;
    }
}

// ---------------------------------------------------------------------------
// Gather aggregation: one warp per node, 4-way edge unroll.
// ---------------------------------------------------------------------------
template<int NV4, int RS>
__global__ __launch_bounds__(256) void agg_kernel(
    const float* __restrict__ Y, float* __restrict__ S,
    const int* __restrict__ csr, const int* __restrict__ off,
    const int* __restrict__ deg, const float* __restrict__ inv, int n)
{
    int w    = (blockIdx.x * blockDim.x + threadIdx.x) >> 5;
    int lane = threadIdx.x & 31;
    if (w >= n) return;
    if (lane >= NV4) return;

    int base = off[w];
    int dg   = deg[w];
    if (dg == 0) return;

    float4 a0 = make_float4(0.f, 0.f, 0.f, 0.f);
    float4 a1 = a0, a2 = a0, a3 = a0;

    int i = 0;
    for (; i + 3 < dg; i += 4) {
        int s0 = __ldg(&csr[base + i + 0]);
        int s1 = __ldg(&csr[base + i + 1]);
        int s2 = __ldg(&csr[base + i + 2]);
        int s3 = __ldg(&csr[base + i + 3]);
        float4 v0 = __ldg(reinterpret_cast<const float4*>(Y + (size_t)s0 * RS) + lane);
        float4 v1 = __ldg(reinterpret_cast<const float4*>(Y + (size_t)s1 * RS) + lane);
        float4 v2 = __ldg(reinterpret_cast<const float4*>(Y + (size_t)s2 * RS) + lane);
        float4 v3 = __ldg(reinterpret_cast<const float4*>(Y + (size_t)s3 * RS) + lane);
        a0.x += v0.x; a0.y += v0.y; a0.z += v0.z; a0.w += v0.w;
        a1.x += v1.x; a1.y += v1.y; a1.z += v1.z; a1.w += v1.w;
        a2.x += v2.x; a2.y += v2.y; a2.z += v2.z; a2.w += v2.w;
        a3.x += v3.x; a3.y += v3.y; a3.z += v3.z; a3.w += v3.w;
    }
    for (; i < dg; i++) {
        int s0 = __ldg(&csr[base + i]);
        float4 v0 = __ldg(reinterpret_cast<const float4*>(Y + (size_t)s0 * RS) + lane);
        a0.x += v0.x; a0.y += v0.y; a0.z += v0.z; a0.w += v0.w;
    }

    float iv = __ldg(&inv[w]);
    float4* sp = reinterpret_cast<float4*>(S + (size_t)w * RS) + lane;
    float4 cur = *sp;
    cur.x += iv * (a0.x + a1.x + a2.x + a3.x);
    cur.y += iv * (a0.y + a1.y + a2.y + a3.y);
    cur.z += iv * (a0.z + a1.z + a2.z + a3.z);
    cur.w += iv * (a0.w + a1.w + a2.w + a3.w);
    *sp = cur;
}

// ---------------------------------------------------------------------------
__global__ void copy_out_kernel(const float* __restrict__ S, float* __restrict__ out, int n) {
    int idx = blockIdx.x * blockDim.x + threadIdx.x;
    int total = n * 47;
    if (idx < total) {
        int r = idx / 47;
        int c = idx - r * 47;
        out[idx] = S[(size_t)r * 48 + c];
    }
}

// ---------------------------------------------------------------------------
extern "C" void kernel_launch(void* const* d_in, const int* in_sizes, int n_in,
                              void* d_out, int out_size)
{
    const float* x   = (const float*)d_in[0];
    const int*   src = (const int*)d_in[1];
    const int*   dst = (const int*)d_in[2];
    const float* ws0 = (const float*)d_in[3];
    const float* wn0 = (const float*)d_in[4];
    const float* b0  = (const float*)d_in[5];
    const float* ws1 = (const float*)d_in[6];
    const float* wn1 = (const float*)d_in[7];
    const float* b1  = (const float*)d_in[8];
    const float* ws2 = (const float*)d_in[9];
    const float* wn2 = (const float*)d_in[10];
    const float* b2  = (const float*)d_in[11];
    float* out = (float*)d_out;

    const int n = in_sizes[0] / 128;   // 100000
    const int e = in_sizes[1];         // 1600000

    float *SA, *SB, *Yb, *inv, *b0p, *b1p, *b2p;
    __nv_bfloat16 *B0, *B1, *B2;
    int *deg, *off, *cur, *csr, *bsum;
    cudaGetSymbolAddress((void**)&SA,   g_SA);
    cudaGetSymbolAddress((void**)&SB,   g_SB);
    cudaGetSymbolAddress((void**)&Yb,   g_Yb);
    cudaGetSymbolAddress((void**)&inv,  g_inv);
    cudaGetSymbolAddress((void**)&deg,  g_deg);
    cudaGetSymbolAddress((void**)&off,  g_off);
    cudaGetSymbolAddress((void**)&cur,  g_cur);
    cudaGetSymbolAddress((void**)&csr,  g_csr);
    cudaGetSymbolAddress((void**)&bsum, g_bsum);
    cudaGetSymbolAddress((void**)&B0,   g_B0);
    cudaGetSymbolAddress((void**)&B1,   g_B1);
    cudaGetSymbolAddress((void**)&B2,   g_B2);
    cudaGetSymbolAddress((void**)&b0p,  g_b0p);
    cudaGetSymbolAddress((void**)&b1p,  g_b1p);
    cudaGetSymbolAddress((void**)&b2p,  g_b2p);

    // dynamic smem: 64KB stage + 32KB Ah/Al + 2*NB*256 B + bias
    const int SMEM_BIG   = 98304 + 2 * 256 * 256 + 512;   // 229888
    const int SMEM_SMALL = 98304 + 2 * 128 * 256 + 512;   // 164352
    cudaFuncSetAttribute(gemm_mma_kernel<256, 128, false>,
                         cudaFuncAttributeMaxDynamicSharedMemorySize, SMEM_BIG);
    cudaFuncSetAttribute(gemm_mma_kernel<256, 128, true>,
                         cudaFuncAttributeMaxDynamicSharedMemorySize, SMEM_BIG);
    cudaFuncSetAttribute(gemm_mma_kernel<128, 48, true>,
                         cudaFuncAttributeMaxDynamicSharedMemorySize, SMEM_SMALL);

    const int ntiles  = (n + 63) / 64;     // 1563
    const int PGRID   = 148;
    const int ablocks = (n * 32 + 255) / 256;
    const int nb = (n + 1023) / 1024;

    // Harness pre-issues 2 launches; ncu -s 5 -c 1 profiles overall #6 = my #4.
    pack_all_kernel<<<(81920 + 255) / 256, 256>>>(
        ws0, wn0, b0, ws1, wn1, b1, ws2, wn2, b2,
        B0, B1, B2, b0p, b1p, b2p);                                   // my 1
    deg_zero_kernel<<<(n + 255) / 256, 256>>>(deg, n);                // my 2
    deg_count_kernel<<<(e + 255) / 256, 256>>>(deg, dst, e);          // my 3

    gemm_mma_kernel<256, 128, false><<<PGRID, 512, SMEM_BIG>>>(
        x, n, ntiles, B0, b0p, SA, Yb);                               // my 4 <- profiled

    scan1_kernel<<<nb, 1024>>>(deg, off, bsum, n);                    // my 5
    scan2_kernel<<<1, 1024>>>(bsum, nb);                              // my 6
    scan3_inv_kernel<<<(n + 255) / 256, 256>>>(off, cur, bsum, deg, inv, n);  // my 7
    csr_fill_kernel<<<(e + 255) / 256, 256>>>(src, dst, cur, csr, e);         // my 8

    agg_kernel<32, 128><<<ablocks, 256>>>(Yb, SA, csr, off, deg, inv, n);     // my 9

    gemm_mma_kernel<256, 128, true><<<PGRID, 512, SMEM_BIG>>>(
        SA, n, ntiles, B1, b1p, SB, Yb);                                      // my 10
    agg_kernel<32, 128><<<ablocks, 256>>>(Yb, SB, csr, off, deg, inv, n);     // my 11

    gemm_mma_kernel<128, 48, true><<<PGRID, 512, SMEM_SMALL>>>(
        SB, n, ntiles, B2, b2p, SA, Yb);                                      // my 12
    agg_kernel<12, 48><<<ablocks, 256>>>(Yb, SA, csr, off, deg, inv, n);      // my 13

    copy_out_kernel<<<(n * 47 + 255) / 256, 256>>>(SA, out, n);               // my 14
}

// round 10
// speedup vs baseline: 2.1591x; 1.3814x over previous
#include <cuda_runtime.h>
#include <cuda_bf16.h>
#include <cuda_fp16.h>
#include <cstdint>
#include <cstddef>

// ---------------------------------------------------------------------------
// GraphSAGE 3-layer forward, fp32 I/O, GB300 (sm_103a host, compute_103 PTX).
//   * transform-then-aggregate (aggregation is linear)
//   * GEMM: warp mma.sync bf16 hi/lo split (3 combos per k-step, fragment
//     reuse), persistent CTAs, B resident, cp.async double-buffered A tiles.
//   * Y (neighbor-transformed, gathered per-edge) stored as fp16: halves the
//     edge-gather traffic; accumulation stays fp32.
//   * per-call CSR build, gather aggregation; layer-2 agg writes output
//     directly (copy_out fused).
// ---------------------------------------------------------------------------

#define NMAX 100000
#define EMAX 1600000

__device__ float  g_SA[(size_t)NMAX * 128];
__device__ float  g_SB[(size_t)NMAX * 128];
__device__ __half g_Yh[(size_t)NMAX * 128];
__device__ float  g_inv[NMAX];
__device__ int    g_deg[NMAX];
__device__ int    g_off[NMAX];
__device__ int    g_cur[NMAX];
__device__ int    g_csr[EMAX];
__device__ int    g_bsum[1024];
// prepacked bf16 weight images (hi image then lo image, swizzled smem layout)
__device__ __nv_bfloat16 g_B0[2 * 256 * 128];
__device__ __nv_bfloat16 g_B1[2 * 256 * 128];
__device__ __nv_bfloat16 g_B2[2 * 128 * 128];
__device__ float g_b0p[128];
__device__ float g_b1p[128];
__device__ float g_b2p[64];

// ---------------------------------------------------------------------------
// PTX helpers
// ---------------------------------------------------------------------------
__device__ __forceinline__ uint32_t smem_u32(const void* p) {
    uint32_t a;
    asm("{ .reg .u64 t; cvta.to.shared.u64 t, %1; cvt.u32.u64 %0, t; }"
        : "=r"(a) : "l"(p));
    return a;
}

__device__ __forceinline__ void ldsm4(uint32_t* r, uint32_t addr) {
    asm volatile("ldmatrix.sync.aligned.m8n8.x4.shared.b16 {%0,%1,%2,%3}, [%4];"
        : "=r"(r[0]), "=r"(r[1]), "=r"(r[2]), "=r"(r[3]) : "r"(addr));
}

__device__ __forceinline__ void mma16816(float* c, const uint32_t* a, const uint32_t* b) {
    asm volatile(
        "mma.sync.aligned.m16n8k16.row.col.f32.bf16.bf16.f32 "
        "{%0,%1,%2,%3}, {%4,%5,%6,%7}, {%8,%9}, {%0,%1,%2,%3};"
        : "+f"(c[0]), "+f"(c[1]), "+f"(c[2]), "+f"(c[3])
        : "r"(a[0]), "r"(a[1]), "r"(a[2]), "r"(a[3]), "r"(b[0]), "r"(b[1]));
}

__device__ __forceinline__ void cpasync16(uint32_t dst, const void* src) {
    asm volatile("cp.async.cg.shared.global [%0], [%1], 16;"
                 :: "r"(dst), "l"(src) : "memory");
}
__device__ __forceinline__ void cpasync_commit() {
    asm volatile("cp.async.commit_group;" ::: "memory");
}
__device__ __forceinline__ void cpasync_wait0() {
    asm volatile("cp.async.wait_group 0;" ::: "memory");
}

__device__ __forceinline__ float2 h2f2(uint32_t u) {
    __half2 h = *reinterpret_cast<__half2*>(&u);
    return __half22float2(h);
}

// ---------------------------------------------------------------------------
// graph-structure kernels
// ---------------------------------------------------------------------------
__global__ void deg_zero_kernel(int* __restrict__ deg, int n) {
    int i = blockIdx.x * blockDim.x + threadIdx.x;
    if (i < n) deg[i] = 0;
}
__global__ void deg_count_kernel(int* __restrict__ deg, const int* __restrict__ dst, int e) {
    int i = blockIdx.x * blockDim.x + threadIdx.x;
    if (i < e) atomicAdd(&deg[dst[i]], 1);
}

__global__ __launch_bounds__(1024) void scan1_kernel(
    const int* __restrict__ deg, int* __restrict__ off, int* __restrict__ bsum, int n)
{
    __shared__ int sh[1024];
    int t = threadIdx.x;
    int i = blockIdx.x * 1024 + t;
    int v = (i < n) ? deg[i] : 0;
    sh[t] = v;
    __syncthreads();
    #pragma unroll
    for (int s = 1; s < 1024; s <<= 1) {
        int x = (t >= s) ? sh[t - s] : 0;
        __syncthreads();
        sh[t] += x;
        __syncthreads();
    }
    if (i < n) off[i] = sh[t] - v;
    if (t == 1023) bsum[blockIdx.x] = sh[t];
}

__global__ __launch_bounds__(1024) void scan2_kernel(int* __restrict__ bsum, int nb) {
    __shared__ int sh[1024];
    int t = threadIdx.x;
    int v = (t < nb) ? bsum[t] : 0;
    sh[t] = v;
    __syncthreads();
    #pragma unroll
    for (int s = 1; s < 1024; s <<= 1) {
        int x = (t >= s) ? sh[t - s] : 0;
        __syncthreads();
        sh[t] += x;
        __syncthreads();
    }
    if (t < nb) bsum[t] = sh[t] - v;
}

__global__ void scan3_inv_kernel(int* __restrict__ off, int* __restrict__ cur,
                                 const int* __restrict__ bsum,
                                 const int* __restrict__ deg,
                                 float* __restrict__ inv, int n) {
    int i = blockIdx.x * blockDim.x + threadIdx.x;
    if (i < n) {
        int o = off[i] + bsum[i >> 10];
        off[i] = o;
        cur[i] = o;
        int d = deg[i];
        inv[i] = 1.0f / (float)(d > 1 ? d : 1);
    }
}

__global__ void csr_fill_kernel(const int* __restrict__ src, const int* __restrict__ dst,
                                int* __restrict__ cur, int* __restrict__ csr, int e) {
    int i = blockIdx.x * blockDim.x + threadIdx.x;
    if (i < e) {
        int d = dst[i];
        int p = atomicAdd(&cur[d], 1);
        csr[p] = src[i];
    }
}

// ---------------------------------------------------------------------------
// weight prepack: bf16 hi/lo images in the smem ldmatrix layout.
//   byte = nrow*256 + (((k>>3) ^ (nrow&7)) << 4) + (k&7)*2
// ---------------------------------------------------------------------------
__device__ __forceinline__ void pack_one(__nv_bfloat16* img, int NB, int nrow, int k, float w) {
    __nv_bfloat16 h = __float2bfloat16(w);
    __nv_bfloat16 l = __float2bfloat16(w - __bfloat162float(h));
    uint32_t off = (uint32_t)nrow * 256u
                 + ((((uint32_t)k >> 3) ^ ((uint32_t)nrow & 7u)) << 4)
                 + ((uint32_t)k & 7u) * 2u;
    char* hi = reinterpret_cast<char*>(img);
    char* lo = reinterpret_cast<char*>(img + (size_t)NB * 128);
    *reinterpret_cast<__nv_bfloat16*>(hi + off) = h;
    *reinterpret_cast<__nv_bfloat16*>(lo + off) = l;
}

__global__ void pack_all_kernel(
    const float* __restrict__ ws0, const float* __restrict__ wn0, const float* __restrict__ b0,
    const float* __restrict__ ws1, const float* __restrict__ wn1, const float* __restrict__ b1,
    const float* __restrict__ ws2, const float* __restrict__ wn2, const float* __restrict__ b2,
    __nv_bfloat16* __restrict__ B0, __nv_bfloat16* __restrict__ B1, __nv_bfloat16* __restrict__ B2,
    float* __restrict__ b0p, float* __restrict__ b1p, float* __restrict__ b2p)
{
    int idx = blockIdx.x * blockDim.x + threadIdx.x;
    if (idx < 32768) {                       // layer 0: NB=256
        int nrow = idx >> 7, k = idx & 127;
        float w = (nrow < 128) ? ws0[k * 128 + nrow] : wn0[k * 128 + (nrow - 128)];
        pack_one(B0, 256, nrow, k, w);
    } else if (idx < 65536) {                // layer 1
        int t = idx - 32768;
        int nrow = t >> 7, k = t & 127;
        float w = (nrow < 128) ? ws1[k * 128 + nrow] : wn1[k * 128 + (nrow - 128)];
        pack_one(B1, 256, nrow, k, w);
    } else if (idx < 65536 + 16384) {        // layer 2: NB=128, WC=47 pad 64
        int t = idx - 65536;
        int nrow = t >> 7, k = t & 127;
        float w = 0.0f;
        if (nrow < 64) { if (nrow < 47) w = ws2[k * 47 + nrow]; }
        else           { int jj = nrow - 64; if (jj < 47) w = wn2[k * 47 + jj]; }
        pack_one(B2, 128, nrow, k, w);
    }
    if (idx < 128) { b0p[idx] = b0[idx]; b1p[idx] = b1[idx]; }
    if (idx < 64)  { b2p[idx] = (idx < 47) ? b2[idx] : 0.0f; }
}

// ---------------------------------------------------------------------------
// PERSISTENT HMMA GEMM, cp.async pipelined, fragment-reuse mma loop.
// Outputs: S (fp32, +bias, stride RS) and Y (fp16, stride RS).
// smem: 0 stage0 | 32768 stage1 | 65536 Ah | 81920 Al | 98304 B | +2*NB*256 bias
// ---------------------------------------------------------------------------
template<int NB, int RS, bool RELU>
__global__ void __launch_bounds__(512, 1) gemm_mma_kernel(
    const float* __restrict__ A, int n, int ntiles,
    const __nv_bfloat16* __restrict__ Bimg, const float* __restrict__ bias,
    float* __restrict__ S, __half* __restrict__ Y)
{
    constexpr int WN  = NB / 8;
    constexpr int NBT = (WN / 16 > 0) ? WN / 16 : 1;
    constexpr int NT  = WN / 8;
    constexpr int HC  = NB / 2;

    extern __shared__ char smem[];
    char*  sB    = smem + 98304;
    float* sBias = reinterpret_cast<float*>(smem + 98304 + 2 * NB * 256);

    const int tid    = threadIdx.x;
    const int wid    = tid >> 5;
    const int lane   = tid & 31;
    const int warp_m = wid & 1;
    const int warp_n = wid >> 1;

    {
        const uint4* src = reinterpret_cast<const uint4*>(Bimg);
        uint4* dst = reinterpret_cast<uint4*>(sB);
        constexpr int CNT = NB * 32;
        #pragma unroll
        for (int i = 0; i < CNT / 512; i++)
            dst[tid + i * 512] = src[tid + i * 512];
        if (tid < HC) sBias[tid] = bias[tid];
    }

    const uint32_t sb  = smem_u32(smem);
    const uint32_t aAh = sb + 65536;
    const uint32_t aAl = sb + 81920;
    const uint32_t aBh = sb + 98304;
    const uint32_t aBl = aBh + NB * 256;

    const int arow = tid >> 3;
    const int acol = (tid & 7) * 16;

    auto loadA_async = [&](int t, int buf) {
        int gr = (t << 6) + arow;
        if (gr > n - 1) gr = n - 1;
        const float* src = A + (size_t)gr * 128 + acol;
        uint32_t dst = sb + buf * 32768 + arow * 512 + acol * 4;
        #pragma unroll
        for (int j = 0; j < 4; j++)
            cpasync16(dst + j * 16, src + j * 4);
        cpasync_commit();
    };

    auto convert = [&](int buf) {
        const float4* sp = reinterpret_cast<const float4*>(
            smem + buf * 32768 + arow * 512 + acol * 4);
        float4 f0 = sp[0], f1 = sp[1], f2 = sp[2], f3 = sp[3];
        float v[16] = {f0.x, f0.y, f0.z, f0.w, f1.x, f1.y, f1.z, f1.w,
                       f2.x, f2.y, f2.z, f2.w, f3.x, f3.y, f3.z, f3.w};
        #pragma unroll
        for (int h = 0; h < 2; h++) {
            struct alignas(16) BF8 { __nv_bfloat16 b[8]; } hh, ll;
            #pragma unroll
            for (int q = 0; q < 8; q++) {
                float x = v[h * 8 + q];
                if (RELU) x = fmaxf(x, 0.0f);
                __nv_bfloat16 hb = __float2bfloat16(x);
                hh.b[q] = hb;
                ll.b[q] = __float2bfloat16(x - __bfloat162float(hb));
            }
            int c16 = (tid & 7) * 2 + h;
            uint32_t off = (uint32_t)arow * 256u
                         + (uint32_t)((c16 ^ (arow & 7)) << 4);
            *reinterpret_cast<BF8*>(smem + 65536 + off) = hh;
            *reinterpret_cast<BF8*>(smem + 81920 + off) = ll;
        }
    };

    int rA[2], swA[2];
    #pragma unroll
    for (int mt = 0; mt < 2; mt++) {
        int row = warp_m * 32 + mt * 16 + (lane & 15);
        rA[mt]  = row * 256;
        swA[mt] = row & 7;
    }
    const int hiA = lane >> 4;
    int rB[NBT], swB[NBT];
    #pragma unroll
    for (int bt = 0; bt < NBT; bt++) {
        int row = warp_n * WN + bt * 16 + ((lane >> 4) << 3) + (lane & 7);
        rB[bt]  = row * 256;
        swB[bt] = row & 7;
    }
    const int hB = (lane >> 3) & 1;

    int buf = 0;
    loadA_async(blockIdx.x, 0);

    for (int t = blockIdx.x; t < ntiles; t += gridDim.x) {
        cpasync_wait0();
        convert(buf);
        int tn = t + gridDim.x;
        if (tn < ntiles) loadA_async(tn, buf ^ 1);
        __syncthreads();

        float acc[2][NT][4];
        #pragma unroll
        for (int mt = 0; mt < 2; mt++)
            #pragma unroll
            for (int nt = 0; nt < NT; nt++)
                #pragma unroll
                for (int q = 0; q < 4; q++)
                    acc[mt][nt][q] = 0.0f;

        #pragma unroll
        for (int s = 0; s < 8; s++) {
            uint32_t ah[2][4], al[2][4];
            #pragma unroll
            for (int mt = 0; mt < 2; mt++) {
                uint32_t ofsA = (uint32_t)(((2 * s + hiA) ^ swA[mt]) << 4);
                ldsm4(ah[mt], aAh + rA[mt] + ofsA);
                ldsm4(al[mt], aAl + rA[mt] + ofsA);
            }
            uint32_t bh[NBT][4], bl[NBT][4];
            #pragma unroll
            for (int bt = 0; bt < NBT; bt++) {
                uint32_t ofsB = (uint32_t)(((2 * s + hB) ^ swB[bt]) << 4);
                ldsm4(bh[bt], aBh + rB[bt] + ofsB);
                ldsm4(bl[bt], aBl + rB[bt] + ofsB);
            }
            #pragma unroll
            for (int mt = 0; mt < 2; mt++)
                #pragma unroll
                for (int nt = 0; nt < NT; nt++) {
                    const uint32_t* bhp = &bh[nt >> 1][(nt & 1) * 2];
                    const uint32_t* blp = &bl[nt >> 1][(nt & 1) * 2];
                    mma16816(acc[mt][nt], ah[mt], bhp);
                    mma16816(acc[mt][nt], al[mt], bhp);
                    mma16816(acc[mt][nt], ah[mt], blp);
                }
        }
        __syncthreads();

        // epilogue for tile t
        int m0 = t << 6;
        #pragma unroll
        for (int mt = 0; mt < 2; mt++) {
            int gr0 = m0 + warp_m * 32 + mt * 16 + (lane >> 2);
            #pragma unroll
            for (int nt = 0; nt < NT; nt++) {
                int J = warp_n * WN + nt * 8 + (lane & 3) * 2;
                #pragma unroll
                for (int rr = 0; rr < 2; rr++) {
                    int gr = gr0 + rr * 8;
                    if (gr >= n) continue;
                    float c0 = acc[mt][nt][rr * 2 + 0];
                    float c1 = acc[mt][nt][rr * 2 + 1];
                    if (J < HC) {
                        if (J < RS) {
                            float2 o = make_float2(c0 + sBias[J], c1 + sBias[J + 1]);
                            *reinterpret_cast<float2*>(S + (size_t)gr * RS + J) = o;
                        }
                    } else {
                        int j2 = J - HC;
                        if (j2 < RS) {
                            __half2 o = __floats2half2_rn(c0, c1);
                            *reinterpret_cast<__half2*>(Y + (size_t)gr * RS + j2) = o;
                        }
                    }
                }
            }
        }
        buf ^= 1;
    }
}

// ---------------------------------------------------------------------------
// Gather aggregation (fp16 Y): one warp per node, 8 edges in flight.
// LANES = RS/4; each lane owns 4 columns (one uint2 = 4 halves per edge).
//   S[node] += inv[node] * sum_{in-edges} Y[src]        (OUT47=false)
//   out[node*47 + c] = that, c < 47                     (OUT47=true)
// ---------------------------------------------------------------------------
template<int LANES, int RS, bool OUT47>
__global__ __launch_bounds__(256) void agg_kernel(
    const __half* __restrict__ Yh, float* __restrict__ S,
    const int* __restrict__ csr, const int* __restrict__ off,
    const int* __restrict__ deg, const float* __restrict__ inv, int n,
    float* __restrict__ out)
{
    int w    = (blockIdx.x * blockDim.x + threadIdx.x) >> 5;
    int lane = threadIdx.x & 31;
    if (w >= n) return;
    if (lane >= LANES) return;

    int base = off[w];
    int dg   = deg[w];
    if (!OUT47 && dg == 0) return;   // S already holds self+bias

    constexpr int RU2 = RS / 4;      // row stride in uint2 units
    const uint2* Yb = reinterpret_cast<const uint2*>(Yh);

    float4 a0 = make_float4(0.f, 0.f, 0.f, 0.f);
    float4 a1 = a0;

    int i = 0;
    for (; i + 7 < dg; i += 8) {
        uint2 v[8];
        #pragma unroll
        for (int k = 0; k < 8; k++) {
            int s = __ldg(&csr[base + i + k]);
            v[k] = __ldg(Yb + (size_t)s * RU2 + lane);
        }
        #pragma unroll
        for (int k = 0; k < 8; k += 2) {
            float2 p0 = h2f2(v[k].x),     p1 = h2f2(v[k].y);
            float2 q0 = h2f2(v[k + 1].x), q1 = h2f2(v[k + 1].y);
            a0.x += p0.x; a0.y += p0.y; a0.z += p1.x; a0.w += p1.y;
            a1.x += q0.x; a1.y += q0.y; a1.z += q1.x; a1.w += q1.y;
        }
    }
    for (; i < dg; i++) {
        int s = __ldg(&csr[base + i]);
        uint2 v = __ldg(Yb + (size_t)s * RU2 + lane);
        float2 p0 = h2f2(v.x), p1 = h2f2(v.y);
        a0.x += p0.x; a0.y += p0.y; a0.z += p1.x; a0.w += p1.y;
    }

    float iv = __ldg(&inv[w]);
    float4 cur = *reinterpret_cast<const float4*>(S + (size_t)w * RS + lane * 4);
    cur.x += iv * (a0.x + a1.x);
    cur.y += iv * (a0.y + a1.y);
    cur.z += iv * (a0.z + a1.z);
    cur.w += iv * (a0.w + a1.w);

    if (!OUT47) {
        *reinterpret_cast<float4*>(S + (size_t)w * RS + lane * 4) = cur;
    } else {
        int col = lane * 4;
        float vals[4] = {cur.x, cur.y, cur.z, cur.w};
        #pragma unroll
        for (int c = 0; c < 4; c++)
            if (col + c < 47) out[(size_t)w * 47 + col + c] = vals[c];
    }
}

// ---------------------------------------------------------------------------
extern "C" void kernel_launch(void* const* d_in, const int* in_sizes, int n_in,
                              void* d_out, int out_size)
{
    const float* x   = (const float*)d_in[0];
    const int*   src = (const int*)d_in[1];
    const int*   dst = (const int*)d_in[2];
    const float* ws0 = (const float*)d_in[3];
    const float* wn0 = (const float*)d_in[4];
    const float* b0  = (const float*)d_in[5];
    const float* ws1 = (const float*)d_in[6];
    const float* wn1 = (const float*)d_in[7];
    const float* b1  = (const float*)d_in[8];
    const float* ws2 = (const float*)d_in[9];
    const float* wn2 = (const float*)d_in[10];
    const float* b2  = (const float*)d_in[11];
    float* out = (float*)d_out;

    const int n = in_sizes[0] / 128;   // 100000
    const int e = in_sizes[1];         // 1600000

    float *SA, *SB, *inv, *b0p, *b1p, *b2p;
    __half* Yh;
    __nv_bfloat16 *B0, *B1, *B2;
    int *deg, *off, *cur, *csr, *bsum;
    cudaGetSymbolAddress((void**)&SA,   g_SA);
    cudaGetSymbolAddress((void**)&SB,   g_SB);
    cudaGetSymbolAddress((void**)&Yh,   g_Yh);
    cudaGetSymbolAddress((void**)&inv,  g_inv);
    cudaGetSymbolAddress((void**)&deg,  g_deg);
    cudaGetSymbolAddress((void**)&off,  g_off);
    cudaGetSymbolAddress((void**)&cur,  g_cur);
    cudaGetSymbolAddress((void**)&csr,  g_csr);
    cudaGetSymbolAddress((void**)&bsum, g_bsum);
    cudaGetSymbolAddress((void**)&B0,   g_B0);
    cudaGetSymbolAddress((void**)&B1,   g_B1);
    cudaGetSymbolAddress((void**)&B2,   g_B2);
    cudaGetSymbolAddress((void**)&b0p,  g_b0p);
    cudaGetSymbolAddress((void**)&b1p,  g_b1p);
    cudaGetSymbolAddress((void**)&b2p,  g_b2p);

    const int SMEM_BIG   = 98304 + 2 * 256 * 256 + 512;   // 229888
    const int SMEM_SMALL = 98304 + 2 * 128 * 256 + 512;   // 164352
    cudaFuncSetAttribute(gemm_mma_kernel<256, 128, false>,
                         cudaFuncAttributeMaxDynamicSharedMemorySize, SMEM_BIG);
    cudaFuncSetAttribute(gemm_mma_kernel<256, 128, true>,
                         cudaFuncAttributeMaxDynamicSharedMemorySize, SMEM_BIG);
    cudaFuncSetAttribute(gemm_mma_kernel<128, 48, true>,
                         cudaFuncAttributeMaxDynamicSharedMemorySize, SMEM_SMALL);

    const int ntiles  = (n + 63) / 64;     // 1563
    const int PGRID   = 148;
    const int ablocks = (n * 32 + 255) / 256;
    const int nb = (n + 1023) / 1024;

    // Harness pre-issues 2 launches; ncu -s 5 -c 1 profiles overall #6 = my #4.
    pack_all_kernel<<<(81920 + 255) / 256, 256>>>(
        ws0, wn0, b0, ws1, wn1, b1, ws2, wn2, b2,
        B0, B1, B2, b0p, b1p, b2p);                                   // my 1
    deg_zero_kernel<<<(n + 255) / 256, 256>>>(deg, n);                // my 2
    deg_count_kernel<<<(e + 255) / 256, 256>>>(deg, dst, e);          // my 3

    gemm_mma_kernel<256, 128, false><<<PGRID, 512, SMEM_BIG>>>(
        x, n, ntiles, B0, b0p, SA, Yh);                               // my 4 <- profiled

    scan1_kernel<<<nb, 1024>>>(deg, off, bsum, n);                    // my 5
    scan2_kernel<<<1, 1024>>>(bsum, nb);                              // my 6
    scan3_inv_kernel<<<(n + 255) / 256, 256>>>(off, cur, bsum, deg, inv, n);  // my 7
    csr_fill_kernel<<<(e + 255) / 256, 256>>>(src, dst, cur, csr, e);         // my 8

    agg_kernel<32, 128, false><<<ablocks, 256>>>(
        Yh, SA, csr, off, deg, inv, n, nullptr);                              // my 9

    gemm_mma_kernel<256, 128, true><<<PGRID, 512, SMEM_BIG>>>(
        SA, n, ntiles, B1, b1p, SB, Yh);                                      // my 10
    agg_kernel<32, 128, false><<<ablocks, 256>>>(
        Yh, SB, csr, off, deg, inv, n, nullptr);                              // my 11

    gemm_mma_kernel<128, 48, true><<<PGRID, 512, SMEM_SMALL>>>(
        SB, n, ntiles, B2, b2p, SA, Yh);                                      // my 12
    agg_kernel<12, 48, true><<<ablocks, 256>>>(
        Yh, SA, csr, off, deg, inv, n, out);                                  // my 13
}

// round 11
// speedup vs baseline: 2.2581x; 1.0458x over previous
#include <cuda_runtime.h>
#include <cuda_bf16.h>
#include <cuda_fp16.h>
#include <cstdint>
#include <cstddef>

// ---------------------------------------------------------------------------
// GraphSAGE 3-layer forward, fp32 I/O, GB300 (sm_103a host, compute_103 PTX).
//   * transform-then-aggregate (aggregation is linear)
//   * GEMM: warp mma.sync bf16 hi/lo split (fragment reuse), persistent CTAs,
//     B resident; CTA split into TWO independent 8-warp groups with private
//     32-row tile pipelines + named barriers -> phase overlap (convert /
//     epilogue of one group hides under the other group's mma).
//   * Y stored fp16 (halves edge-gather traffic); fp32 accumulation.
//   * per-call CSR build, gather aggregation; layer-2 agg writes out directly.
// ---------------------------------------------------------------------------

#define NMAX 100000
#define EMAX 1600000

__device__ float  g_SA[(size_t)NMAX * 128];
__device__ float  g_SB[(size_t)NMAX * 128];
__device__ __half g_Yh[(size_t)NMAX * 128];
__device__ float  g_inv[NMAX];
__device__ int    g_deg[NMAX];
__device__ int    g_off[NMAX];
__device__ int    g_cur[NMAX];
__device__ int    g_csr[EMAX];
__device__ int    g_bsum[1024];
__device__ __nv_bfloat16 g_B0[2 * 256 * 128];
__device__ __nv_bfloat16 g_B1[2 * 256 * 128];
__device__ __nv_bfloat16 g_B2[2 * 128 * 128];
__device__ float g_b0p[128];
__device__ float g_b1p[128];
__device__ float g_b2p[64];

// ---------------------------------------------------------------------------
// PTX helpers
// ---------------------------------------------------------------------------
__device__ __forceinline__ uint32_t smem_u32(const void* p) {
    uint32_t a;
    asm("{ .reg .u64 t; cvta.to.shared.u64 t, %1; cvt.u32.u64 %0, t; }"
        : "=r"(a) : "l"(p));
    return a;
}

__device__ __forceinline__ void ldsm4(uint32_t* r, uint32_t addr) {
    asm volatile("ldmatrix.sync.aligned.m8n8.x4.shared.b16 {%0,%1,%2,%3}, [%4];"
        : "=r"(r[0]), "=r"(r[1]), "=r"(r[2]), "=r"(r[3]) : "r"(addr));
}

__device__ __forceinline__ void mma16816(float* c, const uint32_t* a, const uint32_t* b) {
    asm volatile(
        "mma.sync.aligned.m16n8k16.row.col.f32.bf16.bf16.f32 "
        "{%0,%1,%2,%3}, {%4,%5,%6,%7}, {%8,%9}, {%0,%1,%2,%3};"
        : "+f"(c[0]), "+f"(c[1]), "+f"(c[2]), "+f"(c[3])
        : "r"(a[0]), "r"(a[1]), "r"(a[2]), "r"(a[3]), "r"(b[0]), "r"(b[1]));
}

__device__ __forceinline__ void cpasync16(uint32_t dst, const void* src) {
    asm volatile("cp.async.cg.shared.global [%0], [%1], 16;"
                 :: "r"(dst), "l"(src) : "memory");
}
__device__ __forceinline__ void cpasync_commit() {
    asm volatile("cp.async.commit_group;" ::: "memory");
}
__device__ __forceinline__ void cpasync_wait0() {
    asm volatile("cp.async.wait_group 0;" ::: "memory");
}
__device__ __forceinline__ void bar_named(int id, int cnt) {
    asm volatile("bar.sync %0, %1;" :: "r"(id), "r"(cnt) : "memory");
}

__device__ __forceinline__ float2 h2f2(uint32_t u) {
    __half2 h = *reinterpret_cast<__half2*>(&u);
    return __half22float2(h);
}

// ---------------------------------------------------------------------------
// graph-structure kernels
// ---------------------------------------------------------------------------
__global__ void deg_count_kernel(int* __restrict__ deg, const int* __restrict__ dst, int e) {
    int i = blockIdx.x * blockDim.x + threadIdx.x;
    if (i < e) atomicAdd(&deg[dst[i]], 1);
}

__global__ __launch_bounds__(1024) void scan1_kernel(
    const int* __restrict__ deg, int* __restrict__ off, int* __restrict__ bsum, int n)
{
    __shared__ int sh[1024];
    int t = threadIdx.x;
    int i = blockIdx.x * 1024 + t;
    int v = (i < n) ? deg[i] : 0;
    sh[t] = v;
    __syncthreads();
    #pragma unroll
    for (int s = 1; s < 1024; s <<= 1) {
        int x = (t >= s) ? sh[t - s] : 0;
        __syncthreads();
        sh[t] += x;
        __syncthreads();
    }
    if (i < n) off[i] = sh[t] - v;
    if (t == 1023) bsum[blockIdx.x] = sh[t];
}

__global__ __launch_bounds__(1024) void scan2_kernel(int* __restrict__ bsum, int nb) {
    __shared__ int sh[1024];
    int t = threadIdx.x;
    int v = (t < nb) ? bsum[t] : 0;
    sh[t] = v;
    __syncthreads();
    #pragma unroll
    for (int s = 1; s < 1024; s <<= 1) {
        int x = (t >= s) ? sh[t - s] : 0;
        __syncthreads();
        sh[t] += x;
        __syncthreads();
    }
    if (t < nb) bsum[t] = sh[t] - v;
}

__global__ void scan3_inv_kernel(int* __restrict__ off, int* __restrict__ cur,
                                 const int* __restrict__ bsum,
                                 const int* __restrict__ deg,
                                 float* __restrict__ inv, int n) {
    int i = blockIdx.x * blockDim.x + threadIdx.x;
    if (i < n) {
        int o = off[i] + bsum[i >> 10];
        off[i] = o;
        cur[i] = o;
        int d = deg[i];
        inv[i] = 1.0f / (float)(d > 1 ? d : 1);
    }
}

__global__ void csr_fill_kernel(const int* __restrict__ src, const int* __restrict__ dst,
                                int* __restrict__ cur, int* __restrict__ csr, int e) {
    int i = blockIdx.x * blockDim.x + threadIdx.x;
    if (i < e) {
        int d = dst[i];
        int p = atomicAdd(&cur[d], 1);
        csr[p] = src[i];
    }
}

// ---------------------------------------------------------------------------
// weight prepack (+ deg zero fused): bf16 hi/lo images, ldmatrix layout.
// ---------------------------------------------------------------------------
__device__ __forceinline__ void pack_one(__nv_bfloat16* img, int NB, int nrow, int k, float w) {
    __nv_bfloat16 h = __float2bfloat16(w);
    __nv_bfloat16 l = __float2bfloat16(w - __bfloat162float(h));
    uint32_t off = (uint32_t)nrow * 256u
                 + ((((uint32_t)k >> 3) ^ ((uint32_t)nrow & 7u)) << 4)
                 + ((uint32_t)k & 7u) * 2u;
    char* hi = reinterpret_cast<char*>(img);
    char* lo = reinterpret_cast<char*>(img + (size_t)NB * 128);
    *reinterpret_cast<__nv_bfloat16*>(hi + off) = h;
    *reinterpret_cast<__nv_bfloat16*>(lo + off) = l;
}

__global__ void pack_all_kernel(
    const float* __restrict__ ws0, const float* __restrict__ wn0, const float* __restrict__ b0,
    const float* __restrict__ ws1, const float* __restrict__ wn1, const float* __restrict__ b1,
    const float* __restrict__ ws2, const float* __restrict__ wn2, const float* __restrict__ b2,
    __nv_bfloat16* __restrict__ B0, __nv_bfloat16* __restrict__ B1, __nv_bfloat16* __restrict__ B2,
    float* __restrict__ b0p, float* __restrict__ b1p, float* __restrict__ b2p,
    int* __restrict__ deg, int n)
{
    int idx = blockIdx.x * blockDim.x + threadIdx.x;
    if (idx < n) deg[idx] = 0;
    if (idx < 32768) {
        int nrow = idx >> 7, k = idx & 127;
        float w = (nrow < 128) ? ws0[k * 128 + nrow] : wn0[k * 128 + (nrow - 128)];
        pack_one(B0, 256, nrow, k, w);
    } else if (idx < 65536) {
        int t = idx - 32768;
        int nrow = t >> 7, k = t & 127;
        float w = (nrow < 128) ? ws1[k * 128 + nrow] : wn1[k * 128 + (nrow - 128)];
        pack_one(B1, 256, nrow, k, w);
    } else if (idx < 65536 + 16384) {
        int t = idx - 65536;
        int nrow = t >> 7, k = t & 127;
        float w = 0.0f;
        if (nrow < 64) { if (nrow < 47) w = ws2[k * 47 + nrow]; }
        else           { int jj = nrow - 64; if (jj < 47) w = wn2[k * 47 + jj]; }
        pack_one(B2, 128, nrow, k, w);
    }
    if (idx < 128) { b0p[idx] = b0[idx]; b1p[idx] = b1[idx]; }
    if (idx < 64)  { b2p[idx] = (idx < 47) ? b2[idx] : 0.0f; }
}

// ---------------------------------------------------------------------------
// PERSISTENT HMMA GEMM — dual 8-warp groups, each with a private 32-row tile
// pipeline (cp.async double-buffered stage + Ah/Al) and its own named
// barrier; B + bias shared (resident). Fragment-reuse mma loop (3 combos).
// smem layout:
//   [0, 2*NB*256)                B hi|lo
//   [+0, 512)                    bias
//   per group g (49152 bytes):   stage0 16K | stage1 16K | Ah 8K | Al 8K
// Group g handles tiles t = blockIdx.x*2 + g + i*2*gridDim.x (32 rows each).
// ---------------------------------------------------------------------------
template<int NB, int RS, bool RELU>
__global__ void __launch_bounds__(512, 1) gemm_mma_kernel(
    const float* __restrict__ A, int n, int ntiles,
    const __nv_bfloat16* __restrict__ Bimg, const float* __restrict__ bias,
    float* __restrict__ S, __half* __restrict__ Y)
{
    constexpr int WN  = NB / 8;                     // 32 or 16
    constexpr int NBT = (WN / 16 > 0) ? WN / 16 : 1; // 2 or 1
    constexpr int NT  = WN / 8;                     // 4 or 2
    constexpr int HC  = NB / 2;
    constexpr int BREG = 2 * NB * 256;              // B bytes (hi+lo)

    extern __shared__ char smem[];
    float* sBias = reinterpret_cast<float*>(smem + BREG);

    const int tid    = threadIdx.x;
    const int g      = tid >> 8;        // group 0/1
    const int ltid   = tid & 255;
    const int wgrp   = ltid >> 5;       // warp in group: 0..7 (= warp_n)
    const int lane   = tid & 31;

    // --- B + bias: resident copy, once, all 512 threads ---
    {
        const uint4* srcp = reinterpret_cast<const uint4*>(Bimg);
        uint4* dstp = reinterpret_cast<uint4*>(smem);
        constexpr int CNT = BREG / 16;
        #pragma unroll
        for (int i = 0; i < CNT / 512; i++)
            dstp[tid + i * 512] = srcp[tid + i * 512];
        if (tid < HC) sBias[tid] = bias[tid];
    }

    const uint32_t sb   = smem_u32(smem);
    const int GB        = BREG + 512 + g * 49152;   // group base (bytes)
    const uint32_t aAh  = sb + GB + 32768;
    const uint32_t aAl  = sb + GB + 40960;
    const uint32_t aBh  = sb;
    const uint32_t aBl  = sb + NB * 256;

    const int arow = ltid >> 3;         // 0..31
    const int acol = (ltid & 7) * 16;   // float col base

    auto loadA_async = [&](int t, int buf) {
        int gr = t * 32 + arow;
        if (gr > n - 1) gr = n - 1;
        const float* src = A + (size_t)gr * 128 + acol;
        uint32_t dst = sb + GB + buf * 16384 + arow * 512 + acol * 4;
        #pragma unroll
        for (int j = 0; j < 4; j++)
            cpasync16(dst + j * 16, src + j * 4);
        cpasync_commit();
    };

    auto convert = [&](int buf) {
        const float4* sp = reinterpret_cast<const float4*>(
            smem + GB + buf * 16384 + arow * 512 + acol * 4);
        float4 f0 = sp[0], f1 = sp[1], f2 = sp[2], f3 = sp[3];
        float v[16] = {f0.x, f0.y, f0.z, f0.w, f1.x, f1.y, f1.z, f1.w,
                       f2.x, f2.y, f2.z, f2.w, f3.x, f3.y, f3.z, f3.w};
        #pragma unroll
        for (int h = 0; h < 2; h++) {
            struct alignas(16) BF8 { __nv_bfloat16 b[8]; } hh, ll;
            #pragma unroll
            for (int q = 0; q < 8; q++) {
                float x = v[h * 8 + q];
                if (RELU) x = fmaxf(x, 0.0f);
                __nv_bfloat16 hb = __float2bfloat16(x);
                hh.b[q] = hb;
                ll.b[q] = __float2bfloat16(x - __bfloat162float(hb));
            }
            int c16 = (ltid & 7) * 2 + h;
            uint32_t off = (uint32_t)arow * 256u
                         + (uint32_t)((c16 ^ (arow & 7)) << 4);
            *reinterpret_cast<BF8*>(smem + GB + 32768 + off) = hh;
            *reinterpret_cast<BF8*>(smem + GB + 40960 + off) = ll;
        }
    };

    // --- ldmatrix addressing (fixed per thread) ---
    int rA[2], swA[2];
    #pragma unroll
    for (int mt = 0; mt < 2; mt++) {
        int row = mt * 16 + (lane & 15);    // 0..31
        rA[mt]  = row * 256;
        swA[mt] = row & 7;
    }
    const int hiA = lane >> 4;
    int rB[NBT], swB[NBT];
    #pragma unroll
    for (int bt = 0; bt < NBT; bt++) {
        int row = wgrp * WN + bt * 16 + ((lane >> 4) << 3) + (lane & 7);
        rB[bt]  = row * 256;
        swB[bt] = row & 7;
    }
    const int hB = (lane >> 3) & 1;

    __syncthreads();                    // B/bias visible to all

    const int barid = g + 1;
    const int tstride = 2 * gridDim.x;
    int t0 = blockIdx.x * 2 + g;

    int buf = 0;
    if (t0 < ntiles) loadA_async(t0, 0);

    for (int t = t0; t < ntiles; t += tstride) {
        cpasync_wait0();
        convert(buf);
        int tn = t + tstride;
        if (tn < ntiles) loadA_async(tn, buf ^ 1);
        bar_named(barid, 256);          // group's Ah/Al ready

        float acc[2][NT][4];
        #pragma unroll
        for (int mt = 0; mt < 2; mt++)
            #pragma unroll
            for (int nt = 0; nt < NT; nt++)
                #pragma unroll
                for (int q = 0; q < 4; q++)
                    acc[mt][nt][q] = 0.0f;

        #pragma unroll
        for (int s = 0; s < 8; s++) {
            uint32_t ah[2][4], al[2][4];
            #pragma unroll
            for (int mt = 0; mt < 2; mt++) {
                uint32_t ofsA = (uint32_t)(((2 * s + hiA) ^ swA[mt]) << 4);
                ldsm4(ah[mt], aAh + rA[mt] + ofsA);
                ldsm4(al[mt], aAl + rA[mt] + ofsA);
            }
            uint32_t bh[NBT][4], bl[NBT][4];
            #pragma unroll
            for (int bt = 0; bt < NBT; bt++) {
                uint32_t ofsB = (uint32_t)(((2 * s + hB) ^ swB[bt]) << 4);
                ldsm4(bh[bt], aBh + rB[bt] + ofsB);
                ldsm4(bl[bt], aBl + rB[bt] + ofsB);
            }
            #pragma unroll
            for (int mt = 0; mt < 2; mt++)
                #pragma unroll
                for (int nt = 0; nt < NT; nt++) {
                    const uint32_t* bhp = &bh[nt >> 1][(nt & 1) * 2];
                    const uint32_t* blp = &bl[nt >> 1][(nt & 1) * 2];
                    mma16816(acc[mt][nt], ah[mt], bhp);
                    mma16816(acc[mt][nt], al[mt], bhp);
                    mma16816(acc[mt][nt], ah[mt], blp);
                }
        }
        bar_named(barid, 256);          // group ldsm done; Ah/Al reusable

        // epilogue for tile t (overlaps other group's mma)
        int m0 = t * 32;
        #pragma unroll
        for (int mt = 0; mt < 2; mt++) {
            int gr0 = m0 + mt * 16 + (lane >> 2);
            #pragma unroll
            for (int nt = 0; nt < NT; nt++) {
                int J = wgrp * WN + nt * 8 + (lane & 3) * 2;
                #pragma unroll
                for (int rr = 0; rr < 2; rr++) {
                    int gr = gr0 + rr * 8;
                    if (gr >= n) continue;
                    float c0 = acc[mt][nt][rr * 2 + 0];
                    float c1 = acc[mt][nt][rr * 2 + 1];
                    if (J < HC) {
                        if (J < RS) {
                            float2 o = make_float2(c0 + sBias[J], c1 + sBias[J + 1]);
                            *reinterpret_cast<float2*>(S + (size_t)gr * RS + J) = o;
                        }
                    } else {
                        int j2 = J - HC;
                        if (j2 < RS) {
                            __half2 o = __floats2half2_rn(c0, c1);
                            *reinterpret_cast<__half2*>(Y + (size_t)gr * RS + j2) = o;
                        }
                    }
                }
            }
        }
        buf ^= 1;
    }
}

// ---------------------------------------------------------------------------
// Gather aggregation (fp16 Y): one warp per node, 8 edges in flight.
// ---------------------------------------------------------------------------
template<int LANES, int RS, bool OUT47>
__global__ __launch_bounds__(256) void agg_kernel(
    const __half* __restrict__ Yh, float* __restrict__ S,
    const int* __restrict__ csr, const int* __restrict__ off,
    const int* __restrict__ deg, const float* __restrict__ inv, int n,
    float* __restrict__ out)
{
    int w    = (blockIdx.x * blockDim.x + threadIdx.x) >> 5;
    int lane = threadIdx.x & 31;
    if (w >= n) return;
    if (lane >= LANES) return;

    int base = off[w];
    int dg   = deg[w];
    if (!OUT47 && dg == 0) return;

    constexpr int RU2 = RS / 4;
    const uint2* Yb = reinterpret_cast<const uint2*>(Yh);

    float4 a0 = make_float4(0.f, 0.f, 0.f, 0.f);
    float4 a1 = a0;

    int i = 0;
    for (; i + 7 < dg; i += 8) {
        uint2 v[8];
        #pragma unroll
        for (int k = 0; k < 8; k++) {
            int s = __ldg(&csr[base + i + k]);
            v[k] = __ldg(Yb + (size_t)s * RU2 + lane);
        }
        #pragma unroll
        for (int k = 0; k < 8; k += 2) {
            float2 p0 = h2f2(v[k].x),     p1 = h2f2(v[k].y);
            float2 q0 = h2f2(v[k + 1].x), q1 = h2f2(v[k + 1].y);
            a0.x += p0.x; a0.y += p0.y; a0.z += p1.x; a0.w += p1.y;
            a1.x += q0.x; a1.y += q0.y; a1.z += q1.x; a1.w += q1.y;
        }
    }
    for (; i < dg; i++) {
        int s = __ldg(&csr[base + i]);
        uint2 v = __ldg(Yb + (size_t)s * RU2 + lane);
        float2 p0 = h2f2(v.x), p1 = h2f2(v.y);
        a0.x += p0.x; a0.y += p0.y; a0.z += p1.x; a0.w += p1.y;
    }

    float iv = __ldg(&inv[w]);
    float4 cur = *reinterpret_cast<const float4*>(S + (size_t)w * RS + lane * 4);
    cur.x += iv * (a0.x + a1.x);
    cur.y += iv * (a0.y + a1.y);
    cur.z += iv * (a0.z + a1.z);
    cur.w += iv * (a0.w + a1.w);

    if (!OUT47) {
        *reinterpret_cast<float4*>(S + (size_t)w * RS + lane * 4) = cur;
    } else {
        int col = lane * 4;
        float vals[4] = {cur.x, cur.y, cur.z, cur.w};
        #pragma unroll
        for (int c = 0; c < 4; c++)
            if (col + c < 47) out[(size_t)w * 47 + col + c] = vals[c];
    }
}

// ---------------------------------------------------------------------------
extern "C" void kernel_launch(void* const* d_in, const int* in_sizes, int n_in,
                              void* d_out, int out_size)
{
    const float* x   = (const float*)d_in[0];
    const int*   src = (const int*)d_in[1];
    const int*   dst = (const int*)d_in[2];
    const float* ws0 = (const float*)d_in[3];
    const float* wn0 = (const float*)d_in[4];
    const float* b0  = (const float*)d_in[5];
    const float* ws1 = (const float*)d_in[6];
    const float* wn1 = (const float*)d_in[7];
    const float* b1  = (const float*)d_in[8];
    const float* ws2 = (const float*)d_in[9];
    const float* wn2 = (const float*)d_in[10];
    const float* b2  = (const float*)d_in[11];
    float* out = (float*)d_out;

    const int n = in_sizes[0] / 128;   // 100000
    const int e = in_sizes[1];         // 1600000

    float *SA, *SB, *inv, *b0p, *b1p, *b2p;
    __half* Yh;
    __nv_bfloat16 *B0, *B1, *B2;
    int *deg, *off, *cur, *csr, *bsum;
    cudaGetSymbolAddress((void**)&SA,   g_SA);
    cudaGetSymbolAddress((void**)&SB,   g_SB);
    cudaGetSymbolAddress((void**)&Yh,   g_Yh);
    cudaGetSymbolAddress((void**)&inv,  g_inv);
    cudaGetSymbolAddress((void**)&deg,  g_deg);
    cudaGetSymbolAddress((void**)&off,  g_off);
    cudaGetSymbolAddress((void**)&cur,  g_cur);
    cudaGetSymbolAddress((void**)&csr,  g_csr);
    cudaGetSymbolAddress((void**)&bsum, g_bsum);
    cudaGetSymbolAddress((void**)&B0,   g_B0);
    cudaGetSymbolAddress((void**)&B1,   g_B1);
    cudaGetSymbolAddress((void**)&B2,   g_B2);
    cudaGetSymbolAddress((void**)&b0p,  g_b0p);
    cudaGetSymbolAddress((void**)&b1p,  g_b1p);
    cudaGetSymbolAddress((void**)&b2p,  g_b2p);

    // smem: B(2*NB*256) + bias(512) + 2 groups * 49152
    const int SMEM_BIG   = 2 * 256 * 256 + 512 + 2 * 49152;   // 229888
    const int SMEM_SMALL = 2 * 128 * 256 + 512 + 2 * 49152;   // 164352
    cudaFuncSetAttribute(gemm_mma_kernel<256, 128, false>,
                         cudaFuncAttributeMaxDynamicSharedMemorySize, SMEM_BIG);
    cudaFuncSetAttribute(gemm_mma_kernel<256, 128, true>,
                         cudaFuncAttributeMaxDynamicSharedMemorySize, SMEM_BIG);
    cudaFuncSetAttribute(gemm_mma_kernel<128, 48, true>,
                         cudaFuncAttributeMaxDynamicSharedMemorySize, SMEM_SMALL);

    const int ntiles  = (n + 31) / 32;     // 3125 (32-row tiles)
    const int PGRID   = 148;
    const int ablocks = (n * 32 + 255) / 256;
    const int nb = (n + 1023) / 1024;

    // Harness pre-issues 2 launches; ncu -s 5 -c 1 profiles overall #6 = my #4.
    pack_all_kernel<<<(100000 + 255) / 256, 256>>>(
        ws0, wn0, b0, ws1, wn1, b1, ws2, wn2, b2,
        B0, B1, B2, b0p, b1p, b2p, deg, n);                           // my 1 (+deg zero)
    deg_count_kernel<<<(e + 255) / 256, 256>>>(deg, dst, e);          // my 2
    scan1_kernel<<<nb, 1024>>>(deg, off, bsum, n);                    // my 3

    gemm_mma_kernel<256, 128, false><<<PGRID, 512, SMEM_BIG>>>(
        x, n, ntiles, B0, b0p, SA, Yh);                               // my 4 <- profiled

    scan2_kernel<<<1, 1024>>>(bsum, nb);                              // my 5
    scan3_inv_kernel<<<(n + 255) / 256, 256>>>(off, cur, bsum, deg, inv, n);  // my 6
    csr_fill_kernel<<<(e + 255) / 256, 256>>>(src, dst, cur, csr, e);         // my 7

    agg_kernel<32, 128, false><<<ablocks, 256>>>(
        Yh, SA, csr, off, deg, inv, n, nullptr);                              // my 8

    gemm_mma_kernel<256, 128, true><<<PGRID, 512, SMEM_BIG>>>(
        SA, n, ntiles, B1, b1p, SB, Yh);                                      // my 9
    agg_kernel<32, 128, false><<<ablocks, 256>>>(
        Yh, SB, csr, off, deg, inv, n, nullptr);                              // my 10

    gemm_mma_kernel<128, 48, true><<<PGRID, 512, SMEM_SMALL>>>(
        SB, n, ntiles, B2, b2p, SA, Yh);                                      // my 11
    agg_kernel<12, 48, true><<<ablocks, 256>>>(
        Yh, SA, csr, off, deg, inv, n, out);                                  // my 12
}